// round 2
// baseline (speedup 1.0000x reference)
#include <cuda_runtime.h>
#include <math.h>

#define FULL 0xffffffffu

static const int NB    = 16;
static const int NN    = 1024;
static const int NNODE = NB * NN;   // 16384
static const int MAXN  = 192;       // max neighbors per row (mean ~51, 192 is >>11 sigma)

// -------- static device scratch (no allocations allowed) --------
__device__ float g_u[2][NNODE * 8];     // double-buffered node features u
__device__ float g_s[NNODE * 12];       // GRU hidden state
__device__ float g_deg[NNODE];
__device__ float g_eg[NNODE];
__device__ int   g_nbr[NNODE * MAXN];   // CSR-ish fixed-stride neighbor lists
__device__ int   g_cnt[NNODE];

// -------- zero-init (s starts at 0, eg accumulated via atomics) --------
__global__ void k_zero() {
    int i = blockIdx.x * blockDim.x + threadIdx.x;
    if (i < NNODE) g_eg[i] = 0.f;
    if (i < NNODE * 12) g_s[i] = 0.f;
}

// -------- pass over H: yh_j = sum_i y_i H_ij ; hh_j = sum_i H_ij^2 ; u0 = W1 --------
__global__ void k_col(const float* __restrict__ H, const float* __restrict__ y,
                      const float* __restrict__ W1w, const float* __restrict__ W1b,
                      const float* __restrict__ b1) {
    __shared__ float sy[NN];
    int b = blockIdx.x;
    int j = blockIdx.y * blockDim.x + threadIdx.x;
    for (int t = threadIdx.x; t < NN; t += blockDim.x) sy[t] = y[b * NN + t];
    __syncthreads();
    const float* Hb = H + (size_t)b * NN * NN + j;
    float yh = 0.f, hh = 0.f;
#pragma unroll 8
    for (int i = 0; i < NN; ++i) {
        float h = Hb[(size_t)i * NN];
        yh += sy[i] * h;
        hh += h * h;
    }
    float* up = &g_u[0][(size_t)(b * NN + j) * 8];
#pragma unroll
    for (int c = 0; c < 8; ++c)
        up[c] = W1w[2 * c] * yh + W1w[2 * c + 1] * hh + W1b[c] + b1[c];
}

// -------- pass over adj: build neighbor lists + deg (warp per row) --------
__global__ void k_csr(const float* __restrict__ adj) {
    int row  = blockIdx.x * (blockDim.x >> 5) + (threadIdx.x >> 5);
    int lane = threadIdx.x & 31;
    const float* ar = adj + (size_t)row * NN;
    int base = row * MAXN;
    int cnt  = 0;
    for (int c = 0; c < NN; c += 32) {
        float a = ar[c + lane];
        unsigned m = __ballot_sync(FULL, a != 0.f);
        if (a != 0.f) {
            int pos = cnt + __popc(m & ((1u << lane) - 1u));
            if (pos < MAXN) g_nbr[base + pos] = c + lane;
        }
        cnt += __popc(m);
    }
    if (lane == 0) {
        g_cnt[row] = cnt < MAXN ? cnt : MAXN;
        g_deg[row] = (float)cnt;
    }
}

// -------- eg_i = sum_k H[k,i] * (sum_{j in N(i)} H[k,j]) via SMEM k-tiles --------
// One block per (batch, 32-row k-tile). H tile stored transposed [j][k], stride 33
// (conflict-free both on fill and on the per-neighbor row reads).
__global__ void k_eg(const float* __restrict__ H) {
    extern __shared__ float sm[];          // 1024 * 33 floats = 132 KB
    int b  = blockIdx.x >> 5;
    int k0 = (blockIdx.x & 31) * 32;
    const float* Hb = H + ((size_t)b * NN + k0) * NN;
    for (int idx = threadIdx.x; idx < 32 * NN; idx += blockDim.x) {
        int kk = idx >> 10, j = idx & (NN - 1);
        sm[j * 33 + kk] = Hb[(size_t)kk * NN + j];
    }
    __syncthreads();
    int lane = threadIdx.x & 31;
    int w    = threadIdx.x >> 5;
    int nw   = blockDim.x >> 5;
    for (int i = w; i < NN; i += nw) {
        int row  = b * NN + i;
        int cnt  = g_cnt[row];
        int base = row * MAXN;
        float acc = 0.f;
        for (int c = 0; c < cnt; c += 32) {
            int myj = (c + lane < cnt) ? g_nbr[base + c + lane] : 0;
            int mm  = min(32, cnt - c);
#pragma unroll 4
            for (int t = 0; t < mm; ++t) {
                int j = __shfl_sync(FULL, myj, t);
                acc += sm[j * 33 + lane];   // 128B conflict-free row read
            }
        }
        float v = acc * sm[i * 33 + lane];
#pragma unroll
        for (int o = 16; o > 0; o >>= 1) v += __shfl_down_sync(FULL, v, o);
        if (lane == 0) atomicAdd(&g_eg[row], v);
    }
}

__device__ __forceinline__ float sigf(float x) { return 1.f / (1.f + expf(-x)); }

// -------- fused per-node: msg MLP + GRU + W2 (+ readout on last iter) --------
__global__ void k_node(const float* __restrict__ r, const float* __restrict__ nur,
                       const float* __restrict__ Wm1, const float* __restrict__ Wm1b,
                       const float* __restrict__ Wm2, const float* __restrict__ Wm2b,
                       const float* __restrict__ wih, const float* __restrict__ whh,
                       const float* __restrict__ bih, const float* __restrict__ bhh,
                       const float* __restrict__ W2,  const float* __restrict__ W2b,
                       const float* __restrict__ b2,
                       const float* __restrict__ Wr1, const float* __restrict__ Wr1b,
                       const float* __restrict__ Wr2, const float* __restrict__ Wr2b,
                       int bufin, int last, float* __restrict__ out) {
    __shared__ float w[1690];
    {
        int t = threadIdx.x;
        for (int i = t; i < 384; i += blockDim.x) w[i]        = Wm1[i];
        for (int i = t; i < 16;  i += blockDim.x) w[384 + i]  = Wm1b[i];
        for (int i = t; i < 128; i += blockDim.x) w[400 + i]  = Wm2[i];
        for (int i = t; i < 8;   i += blockDim.x) w[528 + i]  = Wm2b[i];
        for (int i = t; i < 360; i += blockDim.x) w[536 + i]  = wih[i];
        for (int i = t; i < 432; i += blockDim.x) w[896 + i]  = whh[i];
        for (int i = t; i < 36;  i += blockDim.x) w[1328 + i] = bih[i];
        for (int i = t; i < 36;  i += blockDim.x) w[1364 + i] = bhh[i];
        for (int i = t; i < 96;  i += blockDim.x) w[1400 + i] = W2[i];
        for (int i = t; i < 8;   i += blockDim.x) w[1496 + i] = W2b[i] + b2[i];
        for (int i = t; i < 128; i += blockDim.x) w[1512 + i] = Wr1[i];
        for (int i = t; i < 16;  i += blockDim.x) w[1640 + i] = Wr1b[i];
        for (int i = t; i < 32;  i += blockDim.x) w[1656 + i] = Wr2[i];
        for (int i = t; i < 2;   i += blockDim.x) w[1688 + i] = Wr2b[i];
    }
    __syncthreads();
    int node = blockIdx.x * blockDim.x + threadIdx.x;
    if (node >= NNODE) return;
    const float* uin = g_u[bufin];
    float* uout = g_u[bufin ^ 1];

    float u[8];
    {
        const float4* up = (const float4*)(uin + (size_t)node * 8);
        float4 a = up[0], b4 = up[1];
        u[0] = a.x; u[1] = a.y; u[2] = a.z; u[3] = a.w;
        u[4] = b4.x; u[5] = b4.y; u[6] = b4.z; u[7] = b4.w;
    }
    float deg = g_deg[node], eg = g_eg[node];

    float ns[8] = {0, 0, 0, 0, 0, 0, 0, 0};
    int cnt  = g_cnt[node];
    int base = node * MAXN;
    int boff = (node >> 10) << 10;   // batch start in node indexing
    for (int t = 0; t < cnt; ++t) {
        int j = g_nbr[base + t];
        const float4* np = (const float4*)(uin + (size_t)(boff + j) * 8);
        float4 a = np[0], b4 = np[1];
        ns[0] += a.x;  ns[1] += a.y;  ns[2] += a.z;  ns[3] += a.w;
        ns[4] += b4.x; ns[5] += b4.y; ns[6] += b4.z; ns[7] += b4.w;
    }

    // msg MLP: agg = [u*deg (8), ns (8), eg x 8]
    float m[8];
    {
        float hid[16];
#pragma unroll
        for (int t = 0; t < 16; ++t) {
            float h = w[384 + t];
#pragma unroll
            for (int c = 0; c < 8; ++c) h += w[t * 24 + c] * (u[c] * deg);
#pragma unroll
            for (int c = 0; c < 8; ++c) h += w[t * 24 + 8 + c] * ns[c];
#pragma unroll
            for (int c = 0; c < 8; ++c) h += w[t * 24 + 16 + c] * eg;
            hid[t] = fmaxf(h, 0.f);
        }
#pragma unroll
        for (int o = 0; o < 8; ++o) {
            float v = w[528 + o];
#pragma unroll
            for (int t = 0; t < 16; ++t) v += w[400 + o * 16 + t] * hid[t];
            m[o] = v;
        }
    }

    float x[10];
#pragma unroll
    for (int c = 0; c < 8; ++c) x[c] = m[c];
    x[8] = r[node];
    x[9] = fmaxf(nur[node], 1e-10f);

    float s[12];
#pragma unroll
    for (int c = 0; c < 12; ++c) s[c] = g_s[(size_t)node * 12 + c];

    float sn[12];
#pragma unroll
    for (int g = 0; g < 12; ++g) {
        float xr = w[1328 + g], xz = w[1328 + 12 + g], xn = w[1328 + 24 + g];
#pragma unroll
        for (int c = 0; c < 10; ++c) {
            float xv = x[c];
            xr += w[536 + g * 10 + c] * xv;
            xz += w[536 + (12 + g) * 10 + c] * xv;
            xn += w[536 + (24 + g) * 10 + c] * xv;
        }
        float hr = w[1364 + g], hz = w[1364 + 12 + g], hn = w[1364 + 24 + g];
#pragma unroll
        for (int c = 0; c < 12; ++c) {
            float sv = s[c];
            hr += w[896 + g * 12 + c] * sv;
            hz += w[896 + (12 + g) * 12 + c] * sv;
            hn += w[896 + (24 + g) * 12 + c] * sv;
        }
        float rg = sigf(xr + hr);
        float zg = sigf(xz + hz);
        float ng = tanhf(xn + rg * hn);
        sn[g] = (1.f - zg) * ng + zg * s[g];
    }
#pragma unroll
    for (int c = 0; c < 12; ++c) g_s[(size_t)node * 12 + c] = sn[c];

    float un[8];
#pragma unroll
    for (int o = 0; o < 8; ++o) {
        float v = w[1496 + o];
#pragma unroll
        for (int c = 0; c < 12; ++c) v += w[1400 + o * 12 + c] * sn[c];
        un[o] = v;
    }
    {
        float4* op = (float4*)(uout + (size_t)node * 8);
        op[0] = make_float4(un[0], un[1], un[2], un[3]);
        op[1] = make_float4(un[4], un[5], un[6], un[7]);
    }

    if (last) {
        float hid[16];
#pragma unroll
        for (int t = 0; t < 16; ++t) {
            float h = w[1640 + t];
#pragma unroll
            for (int c = 0; c < 8; ++c) h += w[1512 + t * 8 + c] * un[c];
            hid[t] = fmaxf(h, 0.f);
        }
        float l0 = w[1688], l1 = w[1689];
#pragma unroll
        for (int t = 0; t < 16; ++t) {
            l0 += w[1656 + t] * hid[t];
            l1 += w[1656 + 16 + t] * hid[t];
        }
        float mx = fmaxf(l0, l1);
        float e0 = expf(l0 - mx), e1 = expf(l1 - mx);
        float inv = 1.f / (e0 + e1);
        float p0 = e0 * inv, p1 = e1 * inv;
        const float q0 = -0.70710678118654752440f, q1 = 0.70710678118654752440f;
        float xh = p0 * q0 + p1 * q1;
        float nu = p0 * (q0 - xh) * (q0 - xh) + p1 * (q1 - xh) * (q1 - xh);
        nu = fmaxf(nu, 1e-10f);
        out[node]         = xh;
        out[NNODE + node] = nu;
    }
}

extern "C" void kernel_launch(void* const* d_in, const int* in_sizes, int n_in,
                              void* d_out, int out_size) {
    const float* y    = (const float*)d_in[0];
    const float* H    = (const float*)d_in[1];
    const float* r    = (const float*)d_in[2];
    const float* nur  = (const float*)d_in[3];
    const float* adj  = (const float*)d_in[4];
    const float* W1w  = (const float*)d_in[5];
    const float* W1b  = (const float*)d_in[6];
    const float* b1   = (const float*)d_in[7];
    const float* Wm1  = (const float*)d_in[8];
    const float* Wm1b = (const float*)d_in[9];
    const float* Wm2  = (const float*)d_in[10];
    const float* Wm2b = (const float*)d_in[11];
    const float* wih  = (const float*)d_in[12];
    const float* whh  = (const float*)d_in[13];
    const float* bih  = (const float*)d_in[14];
    const float* bhh  = (const float*)d_in[15];
    const float* W2   = (const float*)d_in[16];
    const float* W2b  = (const float*)d_in[17];
    const float* b2   = (const float*)d_in[18];
    const float* Wr1  = (const float*)d_in[19];
    const float* Wr1b = (const float*)d_in[20];
    const float* Wr2  = (const float*)d_in[21];
    const float* Wr2b = (const float*)d_in[22];
    float* out = (float*)d_out;

    const int EG_SMEM = NN * 33 * 4;   // 135168 B dynamic SMEM
    cudaFuncSetAttribute(k_eg, cudaFuncAttributeMaxDynamicSharedMemorySize, EG_SMEM);

    k_zero<<<(NNODE * 12 + 255) / 256, 256>>>();
    k_col<<<dim3(NB, NN / 256), 256>>>(H, y, W1w, W1b, b1);
    k_csr<<<NNODE / 8, 256>>>(adj);
    k_eg<<<NB * 32, 512, EG_SMEM>>>(H);
    k_node<<<NNODE / 256, 256>>>(r, nur, Wm1, Wm1b, Wm2, Wm2b, wih, whh, bih, bhh,
                                 W2, W2b, b2, Wr1, Wr1b, Wr2, Wr2b, 0, 0, out);
    k_node<<<NNODE / 256, 256>>>(r, nur, Wm1, Wm1b, Wm2, Wm2b, wih, whh, bih, bhh,
                                 W2, W2b, b2, Wr1, Wr1b, Wr2, Wr2b, 1, 1, out);
}

// round 3
// speedup vs baseline: 1.4683x; 1.4683x over previous
#include <cuda_runtime.h>
#include <math.h>

#define FULL 0xffffffffu

static const int NB    = 16;
static const int NN    = 1024;
static const int NNODE = NB * NN;   // 16384
static const int MAXN  = 192;       // max neighbors per row (mean ~51)
static const int ROWB  = 132;       // smem row stride in bytes (33 floats)

// -------- static device scratch (no allocations allowed) --------
__device__ float g_u[2][NNODE * 8];     // double-buffered node features u
__device__ float g_s[NNODE * 12];       // GRU hidden state
__device__ float g_deg[NNODE];
__device__ float g_eg[NNODE];
__device__ int   g_nbr[NNODE * MAXN];    // neighbor indices (for k_node)
__device__ int   g_nbroff[NNODE * MAXN]; // neighbor smem byte offsets (for k_eg)
__device__ int   g_cnt[NNODE];

// -------- zero-init (s starts at 0, eg accumulated via atomics) --------
__global__ void k_zero() {
    int i = blockIdx.x * blockDim.x + threadIdx.x;
    if (i < NNODE) g_eg[i] = 0.f;
    if (i < NNODE * 12) g_s[i] = 0.f;
}

// -------- pass over H: yh_j = sum_i y_i H_ij ; hh_j = sum_i H_ij^2 ; u0 = W1 --------
__global__ void k_col(const float* __restrict__ H, const float* __restrict__ y,
                      const float* __restrict__ W1w, const float* __restrict__ W1b,
                      const float* __restrict__ b1) {
    __shared__ float sy[NN];
    int b = blockIdx.x;
    int j = blockIdx.y * blockDim.x + threadIdx.x;
    for (int t = threadIdx.x; t < NN; t += blockDim.x) sy[t] = y[b * NN + t];
    __syncthreads();
    const float* Hb = H + (size_t)b * NN * NN + j;
    float yh = 0.f, hh = 0.f;
#pragma unroll 8
    for (int i = 0; i < NN; ++i) {
        float h = Hb[(size_t)i * NN];
        yh += sy[i] * h;
        hh += h * h;
    }
    float* up = &g_u[0][(size_t)(b * NN + j) * 8];
#pragma unroll
    for (int c = 0; c < 8; ++c)
        up[c] = W1w[2 * c] * yh + W1w[2 * c + 1] * hh + W1b[c] + b1[c];
}

// -------- pass over adj: build neighbor lists + deg (warp per row) --------
// Also writes pre-scaled smem byte offsets, padded to a multiple of 4 with the
// dummy zero row (index 1024) so k_eg can consume int4 chunks with no tail.
__global__ void k_csr(const float* __restrict__ adj) {
    int row  = blockIdx.x * (blockDim.x >> 5) + (threadIdx.x >> 5);
    int lane = threadIdx.x & 31;
    const float* ar = adj + (size_t)row * NN;
    int base = row * MAXN;
    int cnt  = 0;
    for (int c = 0; c < NN; c += 32) {
        float a = ar[c + lane];
        unsigned m = __ballot_sync(FULL, a != 0.f);
        if (a != 0.f) {
            int pos = cnt + __popc(m & ((1u << lane) - 1u));
            if (pos < MAXN) {
                g_nbr[base + pos]    = c + lane;
                g_nbroff[base + pos] = (c + lane) * ROWB;
            }
        }
        cnt += __popc(m);
    }
    int cntc = cnt < MAXN ? cnt : MAXN;
    int cntp = (cntc + 3) & ~3;
    if (lane < cntp - cntc) g_nbroff[base + cntc + lane] = NN * ROWB;  // zero row
    if (lane == 0) {
        g_cnt[row] = cntc;
        g_deg[row] = (float)cnt;
    }
}

// -------- eg_i = sum_k H[k,i] * (sum_{j in N(i)} H[k,j]) via SMEM k-tiles --------
// One block per (batch, 32-row k-tile). Tile transposed [j][k], stride 33 floats
// (conflict-free). Row 1024 is zeros (padding target). 32 warps, warp per node,
// int4 offset loads + 4 independent accumulators.
__global__ void __launch_bounds__(1024, 1) k_eg(const float* __restrict__ H) {
    extern __shared__ float sm[];          // 1025 * 33 floats = 135300 B
    int b  = blockIdx.x >> 5;
    int k0 = (blockIdx.x & 31) * 32;
    const float* Hb = H + ((size_t)b * NN + k0) * NN;
    for (int idx = threadIdx.x; idx < 32 * NN; idx += blockDim.x) {
        int kk = idx >> 10, j = idx & (NN - 1);
        sm[j * 33 + kk] = Hb[(size_t)kk * NN + j];
    }
    for (int t = threadIdx.x; t < 33; t += blockDim.x) sm[NN * 33 + t] = 0.f;
    __syncthreads();
    int lane = threadIdx.x & 31;
    int w    = threadIdx.x >> 5;
    const char* smb = (const char*)sm + lane * 4;
    for (int i = w; i < NN; i += 32) {
        int row = b * NN + i;
        int nq  = ((g_cnt[row] + 3) & ~3) >> 2;
        const int4* off = (const int4*)&g_nbroff[row * MAXN];
        float a0 = 0.f, a1 = 0.f, a2 = 0.f, a3 = 0.f;
#pragma unroll 2
        for (int q = 0; q < nq; ++q) {
            int4 o = off[q];
            a0 += *(const float*)(smb + o.x);
            a1 += *(const float*)(smb + o.y);
            a2 += *(const float*)(smb + o.z);
            a3 += *(const float*)(smb + o.w);
        }
        float v = ((a0 + a1) + (a2 + a3)) * sm[i * 33 + lane];
#pragma unroll
        for (int o = 16; o > 0; o >>= 1) v += __shfl_down_sync(FULL, v, o);
        if (lane == 0) atomicAdd(&g_eg[row], v);
    }
}

__device__ __forceinline__ float sigf(float x) { return 1.f / (1.f + expf(-x)); }

// -------- fused per-node: msg MLP + GRU + W2 (+ readout on last iter) --------
__global__ void k_node(const float* __restrict__ r, const float* __restrict__ nur,
                       const float* __restrict__ Wm1, const float* __restrict__ Wm1b,
                       const float* __restrict__ Wm2, const float* __restrict__ Wm2b,
                       const float* __restrict__ wih, const float* __restrict__ whh,
                       const float* __restrict__ bih, const float* __restrict__ bhh,
                       const float* __restrict__ W2,  const float* __restrict__ W2b,
                       const float* __restrict__ b2,
                       const float* __restrict__ Wr1, const float* __restrict__ Wr1b,
                       const float* __restrict__ Wr2, const float* __restrict__ Wr2b,
                       int bufin, int last, float* __restrict__ out) {
    __shared__ float w[1690];
    {
        int t = threadIdx.x;
        for (int i = t; i < 384; i += blockDim.x) w[i]        = Wm1[i];
        for (int i = t; i < 16;  i += blockDim.x) w[384 + i]  = Wm1b[i];
        for (int i = t; i < 128; i += blockDim.x) w[400 + i]  = Wm2[i];
        for (int i = t; i < 8;   i += blockDim.x) w[528 + i]  = Wm2b[i];
        for (int i = t; i < 360; i += blockDim.x) w[536 + i]  = wih[i];
        for (int i = t; i < 432; i += blockDim.x) w[896 + i]  = whh[i];
        for (int i = t; i < 36;  i += blockDim.x) w[1328 + i] = bih[i];
        for (int i = t; i < 36;  i += blockDim.x) w[1364 + i] = bhh[i];
        for (int i = t; i < 96;  i += blockDim.x) w[1400 + i] = W2[i];
        for (int i = t; i < 8;   i += blockDim.x) w[1496 + i] = W2b[i] + b2[i];
        for (int i = t; i < 128; i += blockDim.x) w[1512 + i] = Wr1[i];
        for (int i = t; i < 16;  i += blockDim.x) w[1640 + i] = Wr1b[i];
        for (int i = t; i < 32;  i += blockDim.x) w[1656 + i] = Wr2[i];
        for (int i = t; i < 2;   i += blockDim.x) w[1688 + i] = Wr2b[i];
    }
    __syncthreads();
    int node = blockIdx.x * blockDim.x + threadIdx.x;
    if (node >= NNODE) return;
    const float* uin = g_u[bufin];
    float* uout = g_u[bufin ^ 1];

    float u[8];
    {
        const float4* up = (const float4*)(uin + (size_t)node * 8);
        float4 a = up[0], b4 = up[1];
        u[0] = a.x; u[1] = a.y; u[2] = a.z; u[3] = a.w;
        u[4] = b4.x; u[5] = b4.y; u[6] = b4.z; u[7] = b4.w;
    }
    float deg = g_deg[node], eg = g_eg[node];

    float ns[8] = {0, 0, 0, 0, 0, 0, 0, 0};
    int cnt  = g_cnt[node];
    int base = node * MAXN;
    int boff = (node >> 10) << 10;   // batch start in node indexing
    for (int t = 0; t < cnt; ++t) {
        int j = g_nbr[base + t];
        const float4* np = (const float4*)(uin + (size_t)(boff + j) * 8);
        float4 a = np[0], b4 = np[1];
        ns[0] += a.x;  ns[1] += a.y;  ns[2] += a.z;  ns[3] += a.w;
        ns[4] += b4.x; ns[5] += b4.y; ns[6] += b4.z; ns[7] += b4.w;
    }

    // msg MLP: agg = [u*deg (8), ns (8), eg x 8]
    float m[8];
    {
        float hid[16];
#pragma unroll
        for (int t = 0; t < 16; ++t) {
            float h = w[384 + t];
#pragma unroll
            for (int c = 0; c < 8; ++c) h += w[t * 24 + c] * (u[c] * deg);
#pragma unroll
            for (int c = 0; c < 8; ++c) h += w[t * 24 + 8 + c] * ns[c];
#pragma unroll
            for (int c = 0; c < 8; ++c) h += w[t * 24 + 16 + c] * eg;
            hid[t] = fmaxf(h, 0.f);
        }
#pragma unroll
        for (int o = 0; o < 8; ++o) {
            float v = w[528 + o];
#pragma unroll
            for (int t = 0; t < 16; ++t) v += w[400 + o * 16 + t] * hid[t];
            m[o] = v;
        }
    }

    float x[10];
#pragma unroll
    for (int c = 0; c < 8; ++c) x[c] = m[c];
    x[8] = r[node];
    x[9] = fmaxf(nur[node], 1e-10f);

    float s[12];
#pragma unroll
    for (int c = 0; c < 12; ++c) s[c] = g_s[(size_t)node * 12 + c];

    float sn[12];
#pragma unroll
    for (int g = 0; g < 12; ++g) {
        float xr = w[1328 + g], xz = w[1328 + 12 + g], xn = w[1328 + 24 + g];
#pragma unroll
        for (int c = 0; c < 10; ++c) {
            float xv = x[c];
            xr += w[536 + g * 10 + c] * xv;
            xz += w[536 + (12 + g) * 10 + c] * xv;
            xn += w[536 + (24 + g) * 10 + c] * xv;
        }
        float hr = w[1364 + g], hz = w[1364 + 12 + g], hn = w[1364 + 24 + g];
#pragma unroll
        for (int c = 0; c < 12; ++c) {
            float sv = s[c];
            hr += w[896 + g * 12 + c] * sv;
            hz += w[896 + (12 + g) * 12 + c] * sv;
            hn += w[896 + (24 + g) * 12 + c] * sv;
        }
        float rg = sigf(xr + hr);
        float zg = sigf(xz + hz);
        float ng = tanhf(xn + rg * hn);
        sn[g] = (1.f - zg) * ng + zg * s[g];
    }
#pragma unroll
    for (int c = 0; c < 12; ++c) g_s[(size_t)node * 12 + c] = sn[c];

    float un[8];
#pragma unroll
    for (int o = 0; o < 8; ++o) {
        float v = w[1496 + o];
#pragma unroll
        for (int c = 0; c < 12; ++c) v += w[1400 + o * 12 + c] * sn[c];
        un[o] = v;
    }
    {
        float4* op = (float4*)(uout + (size_t)node * 8);
        op[0] = make_float4(un[0], un[1], un[2], un[3]);
        op[1] = make_float4(un[4], un[5], un[6], un[7]);
    }

    if (last) {
        float hid[16];
#pragma unroll
        for (int t = 0; t < 16; ++t) {
            float h = w[1640 + t];
#pragma unroll
            for (int c = 0; c < 8; ++c) h += w[1512 + t * 8 + c] * un[c];
            hid[t] = fmaxf(h, 0.f);
        }
        float l0 = w[1688], l1 = w[1689];
#pragma unroll
        for (int t = 0; t < 16; ++t) {
            l0 += w[1656 + t] * hid[t];
            l1 += w[1656 + 16 + t] * hid[t];
        }
        float mx = fmaxf(l0, l1);
        float e0 = expf(l0 - mx), e1 = expf(l1 - mx);
        float inv = 1.f / (e0 + e1);
        float p0 = e0 * inv, p1 = e1 * inv;
        const float q0 = -0.70710678118654752440f, q1 = 0.70710678118654752440f;
        float xh = p0 * q0 + p1 * q1;
        float nu = p0 * (q0 - xh) * (q0 - xh) + p1 * (q1 - xh) * (q1 - xh);
        nu = fmaxf(nu, 1e-10f);
        out[node]         = xh;
        out[NNODE + node] = nu;
    }
}

extern "C" void kernel_launch(void* const* d_in, const int* in_sizes, int n_in,
                              void* d_out, int out_size) {
    const float* y    = (const float*)d_in[0];
    const float* H    = (const float*)d_in[1];
    const float* r    = (const float*)d_in[2];
    const float* nur  = (const float*)d_in[3];
    const float* adj  = (const float*)d_in[4];
    const float* W1w  = (const float*)d_in[5];
    const float* W1b  = (const float*)d_in[6];
    const float* b1   = (const float*)d_in[7];
    const float* Wm1  = (const float*)d_in[8];
    const float* Wm1b = (const float*)d_in[9];
    const float* Wm2  = (const float*)d_in[10];
    const float* Wm2b = (const float*)d_in[11];
    const float* wih  = (const float*)d_in[12];
    const float* whh  = (const float*)d_in[13];
    const float* bih  = (const float*)d_in[14];
    const float* bhh  = (const float*)d_in[15];
    const float* W2   = (const float*)d_in[16];
    const float* W2b  = (const float*)d_in[17];
    const float* b2   = (const float*)d_in[18];
    const float* Wr1  = (const float*)d_in[19];
    const float* Wr1b = (const float*)d_in[20];
    const float* Wr2  = (const float*)d_in[21];
    const float* Wr2b = (const float*)d_in[22];
    float* out = (float*)d_out;

    const int EG_SMEM = (NN + 1) * 33 * 4;   // 135300 B dynamic SMEM
    cudaFuncSetAttribute(k_eg, cudaFuncAttributeMaxDynamicSharedMemorySize, EG_SMEM);

    k_zero<<<(NNODE * 12 + 255) / 256, 256>>>();
    k_col<<<dim3(NB, NN / 256), 256>>>(H, y, W1w, W1b, b1);
    k_csr<<<NNODE / 8, 256>>>(adj);
    k_eg<<<NB * 32, 1024, EG_SMEM>>>(H);
    k_node<<<NNODE / 256, 256>>>(r, nur, Wm1, Wm1b, Wm2, Wm2b, wih, whh, bih, bhh,
                                 W2, W2b, b2, Wr1, Wr1b, Wr2, Wr2b, 0, 0, out);
    k_node<<<NNODE / 256, 256>>>(r, nur, Wm1, Wm1b, Wm2, Wm2b, wih, whh, bih, bhh,
                                 W2, W2b, b2, Wr1, Wr1b, Wr2, Wr2b, 1, 1, out);
}

// round 4
// speedup vs baseline: 1.8029x; 1.2279x over previous
#include <cuda_runtime.h>
#include <math.h>

#define FULL 0xffffffffu

static const int NB    = 16;
static const int NN    = 1024;
static const int NNODE = NB * NN;   // 16384
static const int MAXN  = 192;       // max neighbors per row (mean ~51)
static const int ROWB  = 132;       // k_eg smem row stride in bytes (33 floats)

// -------- static device scratch (no allocations allowed) --------
__device__ float g_u[2][NNODE * 8 + 8]; // double-buffered node features u (+zero row)
__device__ float g_s[NNODE * 12];       // GRU hidden state
__device__ float g_yh[NNODE];
__device__ float g_hh[NNODE];
__device__ float g_deg[NNODE];
__device__ float g_eg[NNODE];
__device__ int   g_nbr[NNODE * MAXN];    // neighbor indices
__device__ int   g_nbroff[NNODE * MAXN]; // neighbor smem byte offsets (k_eg)
__device__ int   g_nbru[NNODE * MAXN];   // neighbor u element offsets (k_node)
__device__ int   g_cnt[NNODE];

// -------- zero-init --------
__global__ void k_zero() {
    int i = blockIdx.x * blockDim.x + threadIdx.x;
    if (i < NNODE) { g_eg[i] = 0.f; g_yh[i] = 0.f; g_hh[i] = 0.f; }
    if (i < NNODE * 12) g_s[i] = 0.f;
    if (i < 8) { g_u[0][NNODE * 8 + i] = 0.f; g_u[1][NNODE * 8 + i] = 0.f; }
}

// -------- H pass: partial yh_j / hh_j over a 128-row k-slice --------
__global__ void k_col(const float* __restrict__ H, const float* __restrict__ y) {
    __shared__ float sy[128];
    int b  = blockIdx.x;
    int j  = blockIdx.y * 128 + threadIdx.x;
    int k0 = blockIdx.z * 128;
    sy[threadIdx.x] = y[b * NN + k0 + threadIdx.x];
    __syncthreads();
    const float* Hb = H + ((size_t)b * NN + k0) * NN + j;
    float yh = 0.f, hh = 0.f;
#pragma unroll 8
    for (int i = 0; i < 128; ++i) {
        float h = Hb[(size_t)i * NN];
        yh += sy[i] * h;
        hh += h * h;
    }
    int node = b * NN + j;
    atomicAdd(&g_yh[node], yh);
    atomicAdd(&g_hh[node], hh);
}

// -------- u0 = W1([yh, hh]) --------
__global__ void k_u0(const float* __restrict__ W1w, const float* __restrict__ W1b,
                     const float* __restrict__ b1) {
    int node = blockIdx.x * blockDim.x + threadIdx.x;
    float yh = g_yh[node], hh = g_hh[node];
    float* up = &g_u[0][(size_t)node * 8];
#pragma unroll
    for (int c = 0; c < 8; ++c)
        up[c] = W1w[2 * c] * yh + W1w[2 * c + 1] * hh + W1b[c] + b1[c];
}

// -------- adj pass: neighbor lists + deg (warp per row), padded to x4 --------
__global__ void k_csr(const float* __restrict__ adj) {
    int row  = blockIdx.x * (blockDim.x >> 5) + (threadIdx.x >> 5);
    int lane = threadIdx.x & 31;
    const float* ar = adj + (size_t)row * NN;
    int base = row * MAXN;
    int boff = (row >> 10) << 10;  // batch start node
    int cnt  = 0;
    for (int c = 0; c < NN; c += 32) {
        float a = ar[c + lane];
        unsigned m = __ballot_sync(FULL, a != 0.f);
        if (a != 0.f) {
            int pos = cnt + __popc(m & ((1u << lane) - 1u));
            if (pos < MAXN) {
                g_nbr[base + pos]    = c + lane;
                g_nbroff[base + pos] = (c + lane) * ROWB;
                g_nbru[base + pos]   = (boff + c + lane) * 8;
            }
        }
        cnt += __popc(m);
    }
    int cntc = cnt < MAXN ? cnt : MAXN;
    int cntp = (cntc + 3) & ~3;
    if (lane < cntp - cntc) {
        g_nbroff[base + cntc + lane] = NN * ROWB;     // zero smem row
        g_nbru[base + cntc + lane]   = NNODE * 8;     // zero u row
    }
    if (lane == 0) {
        g_cnt[row] = cntc;
        g_deg[row] = (float)cnt;
    }
}

// -------- eg_i = sum_k H[k,i] * (sum_{j in N(i)} H[k,j]) via SMEM k-tiles --------
// One block per (batch, 32-row k-tile). Tile transposed [j][k], stride 33 floats.
// Warp processes TWO nodes at once (independent offset/acc streams -> 2x MLP).
__global__ void __launch_bounds__(1024, 1) k_eg(const float* __restrict__ H) {
    extern __shared__ float sm[];          // 1025 * 33 floats = 135300 B
    int b  = blockIdx.x >> 5;
    int k0 = (blockIdx.x & 31) * 32;
    const float* Hb = H + ((size_t)b * NN + k0) * NN;
    for (int idx = threadIdx.x; idx < 32 * NN; idx += blockDim.x) {
        int kk = idx >> 10, j = idx & (NN - 1);
        sm[j * 33 + kk] = Hb[(size_t)kk * NN + j];
    }
    for (int t = threadIdx.x; t < 33; t += blockDim.x) sm[NN * 33 + t] = 0.f;
    __syncthreads();
    int lane = threadIdx.x & 31;
    int w    = threadIdx.x >> 5;
    const char* smb = (const char*)sm + lane * 4;
    for (int i0 = w; i0 < NN; i0 += 64) {
        int i1   = i0 + 32;
        int row0 = b * NN + i0, row1 = b * NN + i1;
        int nq0  = ((g_cnt[row0] + 3) & ~3) >> 2;
        int nq1  = ((g_cnt[row1] + 3) & ~3) >> 2;
        const int4* off0 = (const int4*)&g_nbroff[row0 * MAXN];
        const int4* off1 = (const int4*)&g_nbroff[row1 * MAXN];
        float a0 = 0.f, a1 = 0.f, a2 = 0.f, a3 = 0.f;
        float c0 = 0.f, c1 = 0.f, c2 = 0.f, c3 = 0.f;
        int nqm = nq0 > nq1 ? nq0 : nq1;
#pragma unroll 2
        for (int q = 0; q < nqm; ++q) {
            if (q < nq0) {
                int4 o = off0[q];
                a0 += *(const float*)(smb + o.x);
                a1 += *(const float*)(smb + o.y);
                a2 += *(const float*)(smb + o.z);
                a3 += *(const float*)(smb + o.w);
            }
            if (q < nq1) {
                int4 o = off1[q];
                c0 += *(const float*)(smb + o.x);
                c1 += *(const float*)(smb + o.y);
                c2 += *(const float*)(smb + o.z);
                c3 += *(const float*)(smb + o.w);
            }
        }
        float v0 = ((a0 + a1) + (a2 + a3)) * sm[i0 * 33 + lane];
        float v1 = ((c0 + c1) + (c2 + c3)) * sm[i1 * 33 + lane];
#pragma unroll
        for (int o = 16; o > 0; o >>= 1) {
            v0 += __shfl_down_sync(FULL, v0, o);
            v1 += __shfl_down_sync(FULL, v1, o);
        }
        if (lane == 0) {
            atomicAdd(&g_eg[row0], v0);
            atomicAdd(&g_eg[row1], v1);
        }
    }
}

__device__ __forceinline__ float sigf(float x) { return 1.f / (1.f + expf(-x)); }

// -------- fused per-node: msg MLP + GRU + W2 (+ readout on last iter) --------
__global__ void k_node(const float* __restrict__ r, const float* __restrict__ nur,
                       const float* __restrict__ Wm1, const float* __restrict__ Wm1b,
                       const float* __restrict__ Wm2, const float* __restrict__ Wm2b,
                       const float* __restrict__ wih, const float* __restrict__ whh,
                       const float* __restrict__ bih, const float* __restrict__ bhh,
                       const float* __restrict__ W2,  const float* __restrict__ W2b,
                       const float* __restrict__ b2,
                       const float* __restrict__ Wr1, const float* __restrict__ Wr1b,
                       const float* __restrict__ Wr2, const float* __restrict__ Wr2b,
                       int bufin, int last, float* __restrict__ out) {
    __shared__ float w[1690];
    {
        int t = threadIdx.x;
        for (int i = t; i < 384; i += blockDim.x) w[i]        = Wm1[i];
        for (int i = t; i < 16;  i += blockDim.x) w[384 + i]  = Wm1b[i];
        for (int i = t; i < 128; i += blockDim.x) w[400 + i]  = Wm2[i];
        for (int i = t; i < 8;   i += blockDim.x) w[528 + i]  = Wm2b[i];
        for (int i = t; i < 360; i += blockDim.x) w[536 + i]  = wih[i];
        for (int i = t; i < 432; i += blockDim.x) w[896 + i]  = whh[i];
        for (int i = t; i < 36;  i += blockDim.x) w[1328 + i] = bih[i];
        for (int i = t; i < 36;  i += blockDim.x) w[1364 + i] = bhh[i];
        for (int i = t; i < 96;  i += blockDim.x) w[1400 + i] = W2[i];
        for (int i = t; i < 8;   i += blockDim.x) w[1496 + i] = W2b[i] + b2[i];
        for (int i = t; i < 128; i += blockDim.x) w[1512 + i] = Wr1[i];
        for (int i = t; i < 16;  i += blockDim.x) w[1640 + i] = Wr1b[i];
        for (int i = t; i < 32;  i += blockDim.x) w[1656 + i] = Wr2[i];
        for (int i = t; i < 2;   i += blockDim.x) w[1688 + i] = Wr2b[i];
    }
    __syncthreads();
    int node = blockIdx.x * blockDim.x + threadIdx.x;
    const float* uin = g_u[bufin];
    float* uout = g_u[bufin ^ 1];

    float rv  = r[node];
    float nuv = fmaxf(nur[node], 1e-10f);
    float deg = g_deg[node], eg = g_eg[node];

    float u[8];
    {
        const float4* up = (const float4*)(uin + (size_t)node * 8);
        float4 a = up[0], b4 = up[1];
        u[0] = a.x; u[1] = a.y; u[2] = a.z; u[3] = a.w;
        u[4] = b4.x; u[5] = b4.y; u[6] = b4.z; u[7] = b4.w;
    }

    float ns[8] = {0, 0, 0, 0, 0, 0, 0, 0};
    int nq = ((g_cnt[node] + 3) & ~3) >> 2;
    const int4* off = (const int4*)&g_nbru[node * MAXN];
#pragma unroll 2
    for (int q = 0; q < nq; ++q) {
        int4 o = off[q];
        const float4* p0 = (const float4*)(uin + o.x);
        const float4* p1 = (const float4*)(uin + o.y);
        const float4* p2 = (const float4*)(uin + o.z);
        const float4* p3 = (const float4*)(uin + o.w);
        float4 a0 = p0[0], b0 = p0[1];
        float4 a1 = p1[0], b1 = p1[1];
        float4 a2 = p2[0], b2v = p2[1];
        float4 a3 = p3[0], b3 = p3[1];
        ns[0] += a0.x + a1.x + a2.x + a3.x;
        ns[1] += a0.y + a1.y + a2.y + a3.y;
        ns[2] += a0.z + a1.z + a2.z + a3.z;
        ns[3] += a0.w + a1.w + a2.w + a3.w;
        ns[4] += b0.x + b1.x + b2v.x + b3.x;
        ns[5] += b0.y + b1.y + b2v.y + b3.y;
        ns[6] += b0.z + b1.z + b2v.z + b3.z;
        ns[7] += b0.w + b1.w + b2v.w + b3.w;
    }

    // msg MLP: agg = [u*deg (8), ns (8), eg x 8]
    float m[8];
    {
        float hid[16];
#pragma unroll
        for (int t = 0; t < 16; ++t) {
            float h = w[384 + t];
#pragma unroll
            for (int c = 0; c < 8; ++c) h += w[t * 24 + c] * (u[c] * deg);
#pragma unroll
            for (int c = 0; c < 8; ++c) h += w[t * 24 + 8 + c] * ns[c];
#pragma unroll
            for (int c = 0; c < 8; ++c) h += w[t * 24 + 16 + c] * eg;
            hid[t] = fmaxf(h, 0.f);
        }
#pragma unroll
        for (int o = 0; o < 8; ++o) {
            float v = w[528 + o];
#pragma unroll
            for (int t = 0; t < 16; ++t) v += w[400 + o * 16 + t] * hid[t];
            m[o] = v;
        }
    }

    float x[10];
#pragma unroll
    for (int c = 0; c < 8; ++c) x[c] = m[c];
    x[8] = rv;
    x[9] = nuv;

    float s[12];
#pragma unroll
    for (int c = 0; c < 12; ++c) s[c] = g_s[(size_t)node * 12 + c];

    float sn[12];
#pragma unroll
    for (int g = 0; g < 12; ++g) {
        float xr = w[1328 + g], xz = w[1328 + 12 + g], xn = w[1328 + 24 + g];
#pragma unroll
        for (int c = 0; c < 10; ++c) {
            float xv = x[c];
            xr += w[536 + g * 10 + c] * xv;
            xz += w[536 + (12 + g) * 10 + c] * xv;
            xn += w[536 + (24 + g) * 10 + c] * xv;
        }
        float hr = w[1364 + g], hz = w[1364 + 12 + g], hn = w[1364 + 24 + g];
#pragma unroll
        for (int c = 0; c < 12; ++c) {
            float sv = s[c];
            hr += w[896 + g * 12 + c] * sv;
            hz += w[896 + (12 + g) * 12 + c] * sv;
            hn += w[896 + (24 + g) * 12 + c] * sv;
        }
        float rg = sigf(xr + hr);
        float zg = sigf(xz + hz);
        float ng = tanhf(xn + rg * hn);
        sn[g] = (1.f - zg) * ng + zg * s[g];
    }
#pragma unroll
    for (int c = 0; c < 12; ++c) g_s[(size_t)node * 12 + c] = sn[c];

    float un[8];
#pragma unroll
    for (int o = 0; o < 8; ++o) {
        float v = w[1496 + o];
#pragma unroll
        for (int c = 0; c < 12; ++c) v += w[1400 + o * 12 + c] * sn[c];
        un[o] = v;
    }
    {
        float4* op = (float4*)(uout + (size_t)node * 8);
        op[0] = make_float4(un[0], un[1], un[2], un[3]);
        op[1] = make_float4(un[4], un[5], un[6], un[7]);
    }

    if (last) {
        float hid[16];
#pragma unroll
        for (int t = 0; t < 16; ++t) {
            float h = w[1640 + t];
#pragma unroll
            for (int c = 0; c < 8; ++c) h += w[1512 + t * 8 + c] * un[c];
            hid[t] = fmaxf(h, 0.f);
        }
        float l0 = w[1688], l1 = w[1689];
#pragma unroll
        for (int t = 0; t < 16; ++t) {
            l0 += w[1656 + t] * hid[t];
            l1 += w[1656 + 16 + t] * hid[t];
        }
        float mx = fmaxf(l0, l1);
        float e0 = expf(l0 - mx), e1 = expf(l1 - mx);
        float inv = 1.f / (e0 + e1);
        float p0 = e0 * inv, p1 = e1 * inv;
        const float q0 = -0.70710678118654752440f, q1 = 0.70710678118654752440f;
        float xh = p0 * q0 + p1 * q1;
        float nu = p0 * (q0 - xh) * (q0 - xh) + p1 * (q1 - xh) * (q1 - xh);
        nu = fmaxf(nu, 1e-10f);
        out[node]         = xh;
        out[NNODE + node] = nu;
    }
}

extern "C" void kernel_launch(void* const* d_in, const int* in_sizes, int n_in,
                              void* d_out, int out_size) {
    const float* y    = (const float*)d_in[0];
    const float* H    = (const float*)d_in[1];
    const float* r    = (const float*)d_in[2];
    const float* nur  = (const float*)d_in[3];
    const float* adj  = (const float*)d_in[4];
    const float* W1w  = (const float*)d_in[5];
    const float* W1b  = (const float*)d_in[6];
    const float* b1   = (const float*)d_in[7];
    const float* Wm1  = (const float*)d_in[8];
    const float* Wm1b = (const float*)d_in[9];
    const float* Wm2  = (const float*)d_in[10];
    const float* Wm2b = (const float*)d_in[11];
    const float* wih  = (const float*)d_in[12];
    const float* whh  = (const float*)d_in[13];
    const float* bih  = (const float*)d_in[14];
    const float* bhh  = (const float*)d_in[15];
    const float* W2   = (const float*)d_in[16];
    const float* W2b  = (const float*)d_in[17];
    const float* b2   = (const float*)d_in[18];
    const float* Wr1  = (const float*)d_in[19];
    const float* Wr1b = (const float*)d_in[20];
    const float* Wr2  = (const float*)d_in[21];
    const float* Wr2b = (const float*)d_in[22];
    float* out = (float*)d_out;

    const int EG_SMEM = (NN + 1) * 33 * 4;   // 135300 B dynamic SMEM
    cudaFuncSetAttribute(k_eg, cudaFuncAttributeMaxDynamicSharedMemorySize, EG_SMEM);

    k_zero<<<(NNODE * 12 + 255) / 256, 256>>>();
    k_col<<<dim3(NB, NN / 128, 8), 128>>>(H, y);
    k_csr<<<NNODE / 8, 256>>>(adj);
    k_u0<<<NNODE / 128, 128>>>(W1w, W1b, b1);
    k_eg<<<NB * 32, 1024, EG_SMEM>>>(H);
    k_node<<<NNODE / 128, 128>>>(r, nur, Wm1, Wm1b, Wm2, Wm2b, wih, whh, bih, bhh,
                                 W2, W2b, b2, Wr1, Wr1b, Wr2, Wr2b, 0, 0, out);
    k_node<<<NNODE / 128, 128>>>(r, nur, Wm1, Wm1b, Wm2, Wm2b, wih, whh, bih, bhh,
                                 W2, W2b, b2, Wr1, Wr1b, Wr2, Wr2b, 1, 1, out);
}

// round 5
// speedup vs baseline: 1.8344x; 1.0175x over previous
#include <cuda_runtime.h>
#include <math.h>

#define FULL 0xffffffffu

static const int NB    = 16;
static const int NN    = 1024;
static const int NNODE = NB * NN;   // 16384
static const int MAXN  = 192;       // max neighbors per row (mean ~51)
static const int ROWB  = 132;       // k_eg smem row stride in bytes (33 floats)

// -------- static device scratch (no allocations allowed) --------
__device__ float g_u[2][NNODE * 8 + 8]; // double-buffered node features u (+zero row)
__device__ float g_s[NNODE * 12];       // GRU hidden state
__device__ float g_yhp[8 * NNODE];      // per-slice partials (no atomics)
__device__ float g_hhp[8 * NNODE];
__device__ float g_deg[NNODE];
__device__ float g_eg[NNODE];
__device__ int   g_nbr[NNODE * MAXN];    // neighbor indices
__device__ int   g_nbroff[NNODE * MAXN]; // neighbor smem byte offsets (k_eg)
__device__ int   g_nbru[NNODE * MAXN];   // neighbor u element offsets (k_node)
__device__ int   g_cnt[NNODE];

// -------- zero-init (eg, s, u zero rows) --------
__global__ void k_zero() {
    int i = blockIdx.x * blockDim.x + threadIdx.x;
    if (i < NNODE) g_eg[i] = 0.f;
    if (i < NNODE * 12) g_s[i] = 0.f;
    if (i < 8) { g_u[0][NNODE * 8 + i] = 0.f; g_u[1][NNODE * 8 + i] = 0.f; }
}

// -------- H pass: partial yh_j / hh_j over a 128-row k-slice (plain stores) --------
__global__ void k_col(const float* __restrict__ H, const float* __restrict__ y) {
    __shared__ float sy[128];
    int b  = blockIdx.x;
    int j  = blockIdx.y * 128 + threadIdx.x;
    int k0 = blockIdx.z * 128;
    sy[threadIdx.x] = y[b * NN + k0 + threadIdx.x];
    __syncthreads();
    const float* Hb = H + ((size_t)b * NN + k0) * NN + j;
    float yh = 0.f, hh = 0.f;
#pragma unroll 8
    for (int i = 0; i < 128; ++i) {
        float h = Hb[(size_t)i * NN];
        yh += sy[i] * h;
        hh += h * h;
    }
    int node = b * NN + j;
    g_yhp[blockIdx.z * NNODE + node] = yh;
    g_hhp[blockIdx.z * NNODE + node] = hh;
}

// -------- adj pass: neighbor lists + deg (warp per row), padded to x4 --------
__global__ void k_csr(const float* __restrict__ adj) {
    int row  = blockIdx.x * (blockDim.x >> 5) + (threadIdx.x >> 5);
    int lane = threadIdx.x & 31;
    const float* ar = adj + (size_t)row * NN;
    int base = row * MAXN;
    int boff = (row >> 10) << 10;  // batch start node
    int cnt  = 0;
    for (int c = 0; c < NN; c += 32) {
        float a = ar[c + lane];
        unsigned m = __ballot_sync(FULL, a != 0.f);
        if (a != 0.f) {
            int pos = cnt + __popc(m & ((1u << lane) - 1u));
            if (pos < MAXN) {
                g_nbr[base + pos]    = c + lane;
                g_nbroff[base + pos] = (c + lane) * ROWB;
                g_nbru[base + pos]   = (boff + c + lane) * 8;
            }
        }
        cnt += __popc(m);
    }
    int cntc = cnt < MAXN ? cnt : MAXN;
    int cntp = (cntc + 3) & ~3;
    if (lane < cntp - cntc) {
        g_nbroff[base + cntc + lane] = NN * ROWB;     // zero smem row
        g_nbru[base + cntc + lane]   = NNODE * 8;     // zero u row
    }
    if (lane == 0) {
        g_cnt[row] = cntc;
        g_deg[row] = (float)cnt;
    }
}

// -------- eg_i = sum_k H[k,i] * (sum_{j in N(i)} H[k,j]) via SMEM k-tiles --------
// One block per (batch, 32-row k-tile). Tile transposed [j][k], stride 33 floats.
// Warp processes FOUR nodes at once (4 independent LDG/LDS/FADD streams).
// Blocks 0..127 also finalize u0 = W1([yh,hh]) in the prologue (folded k_u0).
__global__ void __launch_bounds__(1024, 1) k_eg(const float* __restrict__ H,
                                                const float* __restrict__ W1w,
                                                const float* __restrict__ W1b,
                                                const float* __restrict__ b1) {
    extern __shared__ float sm[];          // 1025 * 33 floats = 135300 B
    if (blockIdx.x < 128 && threadIdx.x < 128) {
        int node = blockIdx.x * 128 + threadIdx.x;
        float yh = 0.f, hh = 0.f;
#pragma unroll
        for (int z = 0; z < 8; ++z) {
            yh += g_yhp[z * NNODE + node];
            hh += g_hhp[z * NNODE + node];
        }
        float* up = &g_u[0][(size_t)node * 8];
#pragma unroll
        for (int c = 0; c < 8; ++c)
            up[c] = W1w[2 * c] * yh + W1w[2 * c + 1] * hh + W1b[c] + b1[c];
    }
    int b  = blockIdx.x >> 5;
    int k0 = (blockIdx.x & 31) * 32;
    const float* Hb = H + ((size_t)b * NN + k0) * NN;
    for (int idx = threadIdx.x; idx < 32 * NN; idx += blockDim.x) {
        int kk = idx >> 10, j = idx & (NN - 1);
        sm[j * 33 + kk] = Hb[(size_t)kk * NN + j];
    }
    for (int t = threadIdx.x; t < 33; t += blockDim.x) sm[NN * 33 + t] = 0.f;
    __syncthreads();
    int lane = threadIdx.x & 31;
    int w    = threadIdx.x >> 5;
    const char* smb = (const char*)sm + lane * 4;
    for (int i0 = w; i0 < NN; i0 += 128) {
        int ia = i0, ib = i0 + 32, ic = i0 + 64, id = i0 + 96;
        int ra = b * NN + ia, rb = b * NN + ib, rc = b * NN + ic, rd = b * NN + id;
        int na = (g_cnt[ra] + 3) >> 2;
        int nb2 = (g_cnt[rb] + 3) >> 2;
        int nc = (g_cnt[rc] + 3) >> 2;
        int nd = (g_cnt[rd] + 3) >> 2;
        const int4* oa = (const int4*)&g_nbroff[ra * MAXN];
        const int4* ob = (const int4*)&g_nbroff[rb * MAXN];
        const int4* oc = (const int4*)&g_nbroff[rc * MAXN];
        const int4* od = (const int4*)&g_nbroff[rd * MAXN];
        float aa = 0.f, ab = 0.f, ac = 0.f, ad = 0.f;
        int nm = max(max(na, nb2), max(nc, nd));
        for (int q = 0; q < nm; ++q) {
            if (q < na) {
                int4 o = oa[q];
                float t0 = *(const float*)(smb + o.x), t1 = *(const float*)(smb + o.y);
                float t2 = *(const float*)(smb + o.z), t3 = *(const float*)(smb + o.w);
                aa += (t0 + t1) + (t2 + t3);
            }
            if (q < nb2) {
                int4 o = ob[q];
                float t0 = *(const float*)(smb + o.x), t1 = *(const float*)(smb + o.y);
                float t2 = *(const float*)(smb + o.z), t3 = *(const float*)(smb + o.w);
                ab += (t0 + t1) + (t2 + t3);
            }
            if (q < nc) {
                int4 o = oc[q];
                float t0 = *(const float*)(smb + o.x), t1 = *(const float*)(smb + o.y);
                float t2 = *(const float*)(smb + o.z), t3 = *(const float*)(smb + o.w);
                ac += (t0 + t1) + (t2 + t3);
            }
            if (q < nd) {
                int4 o = od[q];
                float t0 = *(const float*)(smb + o.x), t1 = *(const float*)(smb + o.y);
                float t2 = *(const float*)(smb + o.z), t3 = *(const float*)(smb + o.w);
                ad += (t0 + t1) + (t2 + t3);
            }
        }
        float va = aa * sm[ia * 33 + lane];
        float vb = ab * sm[ib * 33 + lane];
        float vc = ac * sm[ic * 33 + lane];
        float vd = ad * sm[id * 33 + lane];
#pragma unroll
        for (int o = 16; o > 0; o >>= 1) {
            va += __shfl_down_sync(FULL, va, o);
            vb += __shfl_down_sync(FULL, vb, o);
            vc += __shfl_down_sync(FULL, vc, o);
            vd += __shfl_down_sync(FULL, vd, o);
        }
        if (lane == 0) {
            atomicAdd(&g_eg[ra], va);
            atomicAdd(&g_eg[rb], vb);
            atomicAdd(&g_eg[rc], vc);
            atomicAdd(&g_eg[rd], vd);
        }
    }
}

__device__ __forceinline__ float sigf(float x) { return 1.f / (1.f + expf(-x)); }

// -------- fused per-node: msg MLP + GRU + W2 (+ readout on last iter) --------
__global__ void k_node(const float* __restrict__ r, const float* __restrict__ nur,
                       const float* __restrict__ Wm1, const float* __restrict__ Wm1b,
                       const float* __restrict__ Wm2, const float* __restrict__ Wm2b,
                       const float* __restrict__ wih, const float* __restrict__ whh,
                       const float* __restrict__ bih, const float* __restrict__ bhh,
                       const float* __restrict__ W2,  const float* __restrict__ W2b,
                       const float* __restrict__ b2,
                       const float* __restrict__ Wr1, const float* __restrict__ Wr1b,
                       const float* __restrict__ Wr2, const float* __restrict__ Wr2b,
                       int bufin, int last, float* __restrict__ out) {
    __shared__ float w[1690];
    {
        int t = threadIdx.x;
        for (int i = t; i < 384; i += blockDim.x) w[i]        = Wm1[i];
        for (int i = t; i < 16;  i += blockDim.x) w[384 + i]  = Wm1b[i];
        for (int i = t; i < 128; i += blockDim.x) w[400 + i]  = Wm2[i];
        for (int i = t; i < 8;   i += blockDim.x) w[528 + i]  = Wm2b[i];
        for (int i = t; i < 360; i += blockDim.x) w[536 + i]  = wih[i];
        for (int i = t; i < 432; i += blockDim.x) w[896 + i]  = whh[i];
        for (int i = t; i < 36;  i += blockDim.x) w[1328 + i] = bih[i];
        for (int i = t; i < 36;  i += blockDim.x) w[1364 + i] = bhh[i];
        for (int i = t; i < 96;  i += blockDim.x) w[1400 + i] = W2[i];
        for (int i = t; i < 8;   i += blockDim.x) w[1496 + i] = W2b[i] + b2[i];
        for (int i = t; i < 128; i += blockDim.x) w[1512 + i] = Wr1[i];
        for (int i = t; i < 16;  i += blockDim.x) w[1640 + i] = Wr1b[i];
        for (int i = t; i < 32;  i += blockDim.x) w[1656 + i] = Wr2[i];
        for (int i = t; i < 2;   i += blockDim.x) w[1688 + i] = Wr2b[i];
    }
    __syncthreads();
    int node = blockIdx.x * blockDim.x + threadIdx.x;
    const float* uin = g_u[bufin];
    float* uout = g_u[bufin ^ 1];

    float rv  = r[node];
    float nuv = fmaxf(nur[node], 1e-10f);
    float deg = g_deg[node], eg = g_eg[node];

    float u[8];
    {
        const float4* up = (const float4*)(uin + (size_t)node * 8);
        float4 a = up[0], b4 = up[1];
        u[0] = a.x; u[1] = a.y; u[2] = a.z; u[3] = a.w;
        u[4] = b4.x; u[5] = b4.y; u[6] = b4.z; u[7] = b4.w;
    }

    float ns[8] = {0, 0, 0, 0, 0, 0, 0, 0};
    int nq = ((g_cnt[node] + 3) & ~3) >> 2;
    const int4* off = (const int4*)&g_nbru[node * MAXN];
#pragma unroll 2
    for (int q = 0; q < nq; ++q) {
        int4 o = off[q];
        const float4* p0 = (const float4*)(uin + o.x);
        const float4* p1 = (const float4*)(uin + o.y);
        const float4* p2 = (const float4*)(uin + o.z);
        const float4* p3 = (const float4*)(uin + o.w);
        float4 a0 = p0[0], b0 = p0[1];
        float4 a1 = p1[0], b1 = p1[1];
        float4 a2 = p2[0], b2v = p2[1];
        float4 a3 = p3[0], b3 = p3[1];
        ns[0] += a0.x + a1.x + a2.x + a3.x;
        ns[1] += a0.y + a1.y + a2.y + a3.y;
        ns[2] += a0.z + a1.z + a2.z + a3.z;
        ns[3] += a0.w + a1.w + a2.w + a3.w;
        ns[4] += b0.x + b1.x + b2v.x + b3.x;
        ns[5] += b0.y + b1.y + b2v.y + b3.y;
        ns[6] += b0.z + b1.z + b2v.z + b3.z;
        ns[7] += b0.w + b1.w + b2v.w + b3.w;
    }

    // msg MLP: agg = [u*deg (8), ns (8), eg x 8]
    float m[8];
    {
        float hid[16];
#pragma unroll
        for (int t = 0; t < 16; ++t) {
            float h = w[384 + t];
#pragma unroll
            for (int c = 0; c < 8; ++c) h += w[t * 24 + c] * (u[c] * deg);
#pragma unroll
            for (int c = 0; c < 8; ++c) h += w[t * 24 + 8 + c] * ns[c];
#pragma unroll
            for (int c = 0; c < 8; ++c) h += w[t * 24 + 16 + c] * eg;
            hid[t] = fmaxf(h, 0.f);
        }
#pragma unroll
        for (int o = 0; o < 8; ++o) {
            float v = w[528 + o];
#pragma unroll
            for (int t = 0; t < 16; ++t) v += w[400 + o * 16 + t] * hid[t];
            m[o] = v;
        }
    }

    float x[10];
#pragma unroll
    for (int c = 0; c < 8; ++c) x[c] = m[c];
    x[8] = rv;
    x[9] = nuv;

    float s[12];
#pragma unroll
    for (int c = 0; c < 12; ++c) s[c] = g_s[(size_t)node * 12 + c];

    float sn[12];
#pragma unroll
    for (int g = 0; g < 12; ++g) {
        float xr = w[1328 + g], xz = w[1328 + 12 + g], xn = w[1328 + 24 + g];
#pragma unroll
        for (int c = 0; c < 10; ++c) {
            float xv = x[c];
            xr += w[536 + g * 10 + c] * xv;
            xz += w[536 + (12 + g) * 10 + c] * xv;
            xn += w[536 + (24 + g) * 10 + c] * xv;
        }
        float hr = w[1364 + g], hz = w[1364 + 12 + g], hn = w[1364 + 24 + g];
#pragma unroll
        for (int c = 0; c < 12; ++c) {
            float sv = s[c];
            hr += w[896 + g * 12 + c] * sv;
            hz += w[896 + (12 + g) * 12 + c] * sv;
            hn += w[896 + (24 + g) * 12 + c] * sv;
        }
        float rg = sigf(xr + hr);
        float zg = sigf(xz + hz);
        float ng = tanhf(xn + rg * hn);
        sn[g] = (1.f - zg) * ng + zg * s[g];
    }
#pragma unroll
    for (int c = 0; c < 12; ++c) g_s[(size_t)node * 12 + c] = sn[c];

    float un[8];
#pragma unroll
    for (int o = 0; o < 8; ++o) {
        float v = w[1496 + o];
#pragma unroll
        for (int c = 0; c < 12; ++c) v += w[1400 + o * 12 + c] * sn[c];
        un[o] = v;
    }
    {
        float4* op = (float4*)(uout + (size_t)node * 8);
        op[0] = make_float4(un[0], un[1], un[2], un[3]);
        op[1] = make_float4(un[4], un[5], un[6], un[7]);
    }

    if (last) {
        float hid[16];
#pragma unroll
        for (int t = 0; t < 16; ++t) {
            float h = w[1640 + t];
#pragma unroll
            for (int c = 0; c < 8; ++c) h += w[1512 + t * 8 + c] * un[c];
            hid[t] = fmaxf(h, 0.f);
        }
        float l0 = w[1688], l1 = w[1689];
#pragma unroll
        for (int t = 0; t < 16; ++t) {
            l0 += w[1656 + t] * hid[t];
            l1 += w[1656 + 16 + t] * hid[t];
        }
        float mx = fmaxf(l0, l1);
        float e0 = expf(l0 - mx), e1 = expf(l1 - mx);
        float inv = 1.f / (e0 + e1);
        float p0 = e0 * inv, p1 = e1 * inv;
        const float q0 = -0.70710678118654752440f, q1 = 0.70710678118654752440f;
        float xh = p0 * q0 + p1 * q1;
        float nu = p0 * (q0 - xh) * (q0 - xh) + p1 * (q1 - xh) * (q1 - xh);
        nu = fmaxf(nu, 1e-10f);
        out[node]         = xh;
        out[NNODE + node] = nu;
    }
}

extern "C" void kernel_launch(void* const* d_in, const int* in_sizes, int n_in,
                              void* d_out, int out_size) {
    const float* y    = (const float*)d_in[0];
    const float* H    = (const float*)d_in[1];
    const float* r    = (const float*)d_in[2];
    const float* nur  = (const float*)d_in[3];
    const float* adj  = (const float*)d_in[4];
    const float* W1w  = (const float*)d_in[5];
    const float* W1b  = (const float*)d_in[6];
    const float* b1   = (const float*)d_in[7];
    const float* Wm1  = (const float*)d_in[8];
    const float* Wm1b = (const float*)d_in[9];
    const float* Wm2  = (const float*)d_in[10];
    const float* Wm2b = (const float*)d_in[11];
    const float* wih  = (const float*)d_in[12];
    const float* whh  = (const float*)d_in[13];
    const float* bih  = (const float*)d_in[14];
    const float* bhh  = (const float*)d_in[15];
    const float* W2   = (const float*)d_in[16];
    const float* W2b  = (const float*)d_in[17];
    const float* b2   = (const float*)d_in[18];
    const float* Wr1  = (const float*)d_in[19];
    const float* Wr1b = (const float*)d_in[20];
    const float* Wr2  = (const float*)d_in[21];
    const float* Wr2b = (const float*)d_in[22];
    float* out = (float*)d_out;

    const int EG_SMEM = (NN + 1) * 33 * 4;   // 135300 B dynamic SMEM
    cudaFuncSetAttribute(k_eg, cudaFuncAttributeMaxDynamicSharedMemorySize, EG_SMEM);

    k_zero<<<(NNODE * 12 + 255) / 256, 256>>>();
    k_col<<<dim3(NB, NN / 128, 8), 128>>>(H, y);
    k_csr<<<NNODE / 8, 256>>>(adj);
    k_eg<<<NB * 32, 1024, EG_SMEM>>>(H, W1w, W1b, b1);
    k_node<<<NNODE / 128, 128>>>(r, nur, Wm1, Wm1b, Wm2, Wm2b, wih, whh, bih, bhh,
                                 W2, W2b, b2, Wr1, Wr1b, Wr2, Wr2b, 0, 0, out);
    k_node<<<NNODE / 128, 128>>>(r, nur, Wm1, Wm1b, Wm2, Wm2b, wih, whh, bih, bhh,
                                 W2, W2b, b2, Wr1, Wr1b, Wr2, Wr2b, 1, 1, out);
}

// round 8
// speedup vs baseline: 2.2028x; 1.2008x over previous
#include <cuda_runtime.h>
#include <cuda_fp16.h>
#include <stdint.h>
#include <math.h>

#define FULL 0xffffffffu

static const int NB    = 16;
static const int NN    = 1024;
static const int NNODE = NB * NN;   // 16384
static const int MAXN  = 192;

// -------- static device scratch (no allocations allowed) --------
__device__ float g_u[2][NNODE * 8 + 8];
__device__ float g_s[NNODE * 12];
__device__ float g_yhp[8 * NNODE];
__device__ float g_hhp[8 * NNODE];
__device__ float g_deg[NNODE];
__device__ float g_eg[NNODE];
__device__ int   g_nbru[NNODE * MAXN];
__device__ int   g_cnt[NNODE];
__device__ __half g_Hhi[(size_t)NB * NN * NN];
__device__ __half g_Hlo[(size_t)NB * NN * NN];
__device__ __half g_adjh[(size_t)NB * NN * NN];

__device__ __forceinline__ uint32_t sm_u32(const void* p) {
    uint32_t a;
    asm("{ .reg .u64 t; cvta.to.shared.u64 t, %1; cvt.u32.u64 %0, t; }"
        : "=r"(a) : "l"(p));
    return a;
}
__device__ __forceinline__ uint32_t lds32(uint32_t a) {
    uint32_t v;
    asm volatile("ld.shared.b32 %0, [%1];" : "=r"(v) : "r"(a));
    return v;
}
__device__ __forceinline__ void cpasync16(uint32_t dst, const void* src) {
    asm volatile("cp.async.cg.shared.global [%0], [%1], 16;"
                 :: "r"(dst), "l"(src) : "memory");
}
__device__ __forceinline__ void mma16816(float* c, uint32_t a0, uint32_t a1,
                                         uint32_t a2, uint32_t a3,
                                         uint32_t b0, uint32_t b1) {
    asm volatile(
        "mma.sync.aligned.m16n8k16.row.col.f32.f16.f16.f32 "
        "{%0,%1,%2,%3}, {%4,%5,%6,%7}, {%8,%9}, {%0,%1,%2,%3};"
        : "+f"(c[0]), "+f"(c[1]), "+f"(c[2]), "+f"(c[3])
        : "r"(a0), "r"(a1), "r"(a2), "r"(a3), "r"(b0), "r"(b1));
}

// -------- zero-init --------
__global__ void k_zero() {
    int i = blockIdx.x * blockDim.x + threadIdx.x;
    if (i < NNODE) g_eg[i] = 0.f;
    if (i < NNODE * 12) g_s[i] = 0.f;
    if (i < 8) { g_u[0][NNODE * 8 + i] = 0.f; g_u[1][NNODE * 8 + i] = 0.f; }
}

// -------- one pass over H: yh/hh partials + fp16 hi/lo split --------
__global__ void k_convcol(const float* __restrict__ H, const float* __restrict__ y) {
    __shared__ float sy[128];
    int b = blockIdx.x, j = blockIdx.y * 128 + threadIdx.x, k0 = blockIdx.z * 128;
    sy[threadIdx.x] = y[b * NN + k0 + threadIdx.x];
    __syncthreads();
    const float* Hb = H + ((size_t)b * NN + k0) * NN + j;
    __half* hi = g_Hhi + ((size_t)b * NN + k0) * NN + j;
    __half* lo = g_Hlo + ((size_t)b * NN + k0) * NN + j;
    float yh = 0.f, hh = 0.f;
#pragma unroll 4
    for (int i = 0; i < 128; ++i) {
        float h = Hb[(size_t)i * NN];
        __half hb = __float2half(h);
        hi[(size_t)i * NN] = hb;
        lo[(size_t)i * NN] = __float2half(h - __half2float(hb));
        yh += sy[i] * h;
        hh += h * h;
    }
    int node = b * NN + j;
    g_yhp[blockIdx.z * NNODE + node] = yh;
    g_hhp[blockIdx.z * NNODE + node] = hh;
}

// -------- adj pass: neighbor lists + deg + fp16 adj + u0 --------
__global__ void k_csr(const float* __restrict__ adj, const float* __restrict__ W1w,
                      const float* __restrict__ W1b, const float* __restrict__ b1) {
    int row  = blockIdx.x * (blockDim.x >> 5) + (threadIdx.x >> 5);
    int lane = threadIdx.x & 31;
    const float* ar = adj + (size_t)row * NN;
    __half* ah = g_adjh + (size_t)row * NN;
    const __half ONE = __float2half(1.f), ZERO = __float2half(0.f);
    int base = row * MAXN;
    int boff = (row >> 10) << 10;
    int cnt  = 0;
    for (int c = 0; c < NN; c += 32) {
        float a = ar[c + lane];
        ah[c + lane] = (a != 0.f) ? ONE : ZERO;
        unsigned m = __ballot_sync(FULL, a != 0.f);
        if (a != 0.f) {
            int pos = cnt + __popc(m & ((1u << lane) - 1u));
            if (pos < MAXN) g_nbru[base + pos] = (boff + c + lane) * 8;
        }
        cnt += __popc(m);
    }
    int cntc = cnt < MAXN ? cnt : MAXN;
    int cntp = (cntc + 3) & ~3;
    if (lane < cntp - cntc) g_nbru[base + cntc + lane] = NNODE * 8;  // zero u row
    if (lane == 0) {
        g_cnt[row] = cntc;
        g_deg[row] = (float)cnt;
    }
    if (lane < 8) {
        float yh = 0.f, hh = 0.f;
#pragma unroll
        for (int z = 0; z < 8; ++z) {
            yh += g_yhp[z * NNODE + row];
            hh += g_hhp[z * NNODE + row];
        }
        g_u[0][(size_t)row * 8 + lane] =
            W1w[2 * lane] * yh + W1w[2 * lane + 1] * hh + W1b[lane] + b1[lane];
    }
}

// -------- eg via mma.sync: T = (Hhi+Hlo) @ adj^T, eg_i = sum_k H[k,i]*T[k,i] --
// CTA = 128x128 tile (m = k-rows, n = i-cols) of batch b. 8 warps as 2x4.
// K (= j) in 32-wide chunks, cp.async double-buffered. Tiles: row stride 40
// halves (80B) -> conflict-free b32 fragment loads (banks 20g+t distinct).
static const int TSTRIDE = 80;      // bytes per tile row
static const int TILEB   = 128 * TSTRIDE;   // 10240 B per tile
static const int BUFB    = 3 * TILEB;       // Ahi, Alo, B

__global__ void __launch_bounds__(256, 2) k_gemm(const float* __restrict__ H) {
    extern __shared__ __align__(16) char smb[];
    const int tid = threadIdx.x, wid = tid >> 5, lane = tid & 31;
    const int g = lane >> 2, t = lane & 3;
    const int b = blockIdx.z;
    const int i0 = blockIdx.x * 128, k0 = blockIdx.y * 128;
    const int wm = wid & 1, wn = wid >> 1;

    const __half* Ahi = g_Hhi  + ((size_t)b * NN + k0) * NN;
    const __half* Alo = g_Hlo  + ((size_t)b * NN + k0) * NN;
    const __half* Bad = g_adjh + ((size_t)b * NN + i0) * NN;
    const uint32_t sbase = sm_u32(smb);

    float acc[4][4][4];
#pragma unroll
    for (int a = 0; a < 4; ++a)
#pragma unroll
        for (int n = 0; n < 4; ++n)
#pragma unroll
            for (int r = 0; r < 4; ++r) acc[a][n][r] = 0.f;

    // --- cp.async fill of chunk c into buffer c&1 ---
    auto issue = [&](int c) {
        int j0 = c * 32;
        uint32_t tb = sbase + (c & 1) * BUFB;
#pragma unroll
        for (int q = 0; q < 2; ++q) {
            int idx = tid + q * 256;
            int row = idx >> 2, quad = idx & 3;
            uint32_t so = tb + row * TSTRIDE + quad * 16;
            cpasync16(so,             Ahi + (size_t)row * NN + j0 + quad * 8);
            cpasync16(so + TILEB,     Alo + (size_t)row * NN + j0 + quad * 8);
            cpasync16(so + 2 * TILEB, Bad + (size_t)row * NN + j0 + quad * 8);
        }
        asm volatile("cp.async.commit_group;" ::: "memory");
    };

    issue(0);
    for (int c = 0; c < 32; ++c) {
        if (c < 31) {
            issue(c + 1);
            asm volatile("cp.async.wait_group 1;" ::: "memory");
        } else {
            asm volatile("cp.async.wait_group 0;" ::: "memory");
        }
        __syncthreads();
        uint32_t sA = sbase + (c & 1) * BUFB;
        uint32_t sL = sA + TILEB, sB = sA + 2 * TILEB;
#pragma unroll
        for (int ks = 0; ks < 2; ++ks) {
            uint32_t bfr[4][2];
#pragma unroll
            for (int ni = 0; ni < 4; ++ni) {
                uint32_t ba = sB + (wn * 32 + ni * 8 + g) * TSTRIDE + ks * 32 + t * 4;
                bfr[ni][0] = lds32(ba);
                bfr[ni][1] = lds32(ba + 16);
            }
#pragma unroll
            for (int sp = 0; sp < 2; ++sp) {
                uint32_t sa = sp ? sL : sA;
#pragma unroll
                for (int mi = 0; mi < 4; ++mi) {
                    int m = wm * 64 + mi * 16;
                    uint32_t r0 = sa + (m + g) * TSTRIDE + ks * 32 + t * 4;
                    uint32_t r1 = r0 + 8 * TSTRIDE;
                    uint32_t a0 = lds32(r0), a1 = lds32(r1);
                    uint32_t a2 = lds32(r0 + 16), a3 = lds32(r1 + 16);
#pragma unroll
                    for (int ni = 0; ni < 4; ++ni)
                        mma16816(acc[mi][ni], a0, a1, a2, a3, bfr[ni][0], bfr[ni][1]);
                }
            }
        }
        __syncthreads();
    }

    // --- epilogue: eg[i0+n] += sum_m H[k0+m, i0+n] * D[m, n] ---
    const float* Hb = H + ((size_t)b * NN + k0) * NN + i0;
#pragma unroll
    for (int ni = 0; ni < 4; ++ni) {
        int col = wn * 32 + ni * 8 + 2 * t;
        float p0 = 0.f, p1 = 0.f;
#pragma unroll
        for (int mi = 0; mi < 4; ++mi) {
            int m = wm * 64 + mi * 16;
            float2 h0 = *(const float2*)(Hb + (size_t)(m + g) * NN + col);
            float2 h1 = *(const float2*)(Hb + (size_t)(m + g + 8) * NN + col);
            p0 += acc[mi][ni][0] * h0.x + acc[mi][ni][2] * h1.x;
            p1 += acc[mi][ni][1] * h0.y + acc[mi][ni][3] * h1.y;
        }
#pragma unroll
        for (int o = 4; o < 32; o <<= 1) {
            p0 += __shfl_xor_sync(FULL, p0, o);
            p1 += __shfl_xor_sync(FULL, p1, o);
        }
        if (g == 0) {
            atomicAdd(&g_eg[b * NN + i0 + col], p0);
            atomicAdd(&g_eg[b * NN + i0 + col + 1], p1);
        }
    }
}

__device__ __forceinline__ float sigf(float x) { return 1.f / (1.f + expf(-x)); }

// -------- fused per-node: msg MLP + GRU + W2 (+ readout on last iter) --------
__global__ void k_node(const float* __restrict__ r, const float* __restrict__ nur,
                       const float* __restrict__ Wm1, const float* __restrict__ Wm1b,
                       const float* __restrict__ Wm2, const float* __restrict__ Wm2b,
                       const float* __restrict__ wih, const float* __restrict__ whh,
                       const float* __restrict__ bih, const float* __restrict__ bhh,
                       const float* __restrict__ W2,  const float* __restrict__ W2b,
                       const float* __restrict__ b2,
                       const float* __restrict__ Wr1, const float* __restrict__ Wr1b,
                       const float* __restrict__ Wr2, const float* __restrict__ Wr2b,
                       int bufin, int last, float* __restrict__ out) {
    __shared__ float w[1690];
    {
        int t = threadIdx.x;
        for (int i = t; i < 384; i += blockDim.x) w[i]        = Wm1[i];
        for (int i = t; i < 16;  i += blockDim.x) w[384 + i]  = Wm1b[i];
        for (int i = t; i < 128; i += blockDim.x) w[400 + i]  = Wm2[i];
        for (int i = t; i < 8;   i += blockDim.x) w[528 + i]  = Wm2b[i];
        for (int i = t; i < 360; i += blockDim.x) w[536 + i]  = wih[i];
        for (int i = t; i < 432; i += blockDim.x) w[896 + i]  = whh[i];
        for (int i = t; i < 36;  i += blockDim.x) w[1328 + i] = bih[i];
        for (int i = t; i < 36;  i += blockDim.x) w[1364 + i] = bhh[i];
        for (int i = t; i < 96;  i += blockDim.x) w[1400 + i] = W2[i];
        for (int i = t; i < 8;   i += blockDim.x) w[1496 + i] = W2b[i] + b2[i];
        for (int i = t; i < 128; i += blockDim.x) w[1512 + i] = Wr1[i];
        for (int i = t; i < 16;  i += blockDim.x) w[1640 + i] = Wr1b[i];
        for (int i = t; i < 32;  i += blockDim.x) w[1656 + i] = Wr2[i];
        for (int i = t; i < 2;   i += blockDim.x) w[1688 + i] = Wr2b[i];
    }
    __syncthreads();
    int node = blockIdx.x * blockDim.x + threadIdx.x;
    const float* uin = g_u[bufin];
    float* uout = g_u[bufin ^ 1];

    float rv  = r[node];
    float nuv = fmaxf(nur[node], 1e-10f);
    float deg = g_deg[node], eg = g_eg[node];

    float u[8];
    {
        const float4* up = (const float4*)(uin + (size_t)node * 8);
        float4 a = up[0], b4 = up[1];
        u[0] = a.x; u[1] = a.y; u[2] = a.z; u[3] = a.w;
        u[4] = b4.x; u[5] = b4.y; u[6] = b4.z; u[7] = b4.w;
    }

    float ns[8] = {0, 0, 0, 0, 0, 0, 0, 0};
    int nq = ((g_cnt[node] + 3) & ~3) >> 2;
    const int4* off = (const int4*)&g_nbru[node * MAXN];
#pragma unroll 2
    for (int q = 0; q < nq; ++q) {
        int4 o = off[q];
        const float4* p0 = (const float4*)(uin + o.x);
        const float4* p1 = (const float4*)(uin + o.y);
        const float4* p2 = (const float4*)(uin + o.z);
        const float4* p3 = (const float4*)(uin + o.w);
        float4 a0 = p0[0], b0 = p0[1];
        float4 a1 = p1[0], b1 = p1[1];
        float4 a2 = p2[0], b2v = p2[1];
        float4 a3 = p3[0], b3 = p3[1];
        ns[0] += a0.x + a1.x + a2.x + a3.x;
        ns[1] += a0.y + a1.y + a2.y + a3.y;
        ns[2] += a0.z + a1.z + a2.z + a3.z;
        ns[3] += a0.w + a1.w + a2.w + a3.w;
        ns[4] += b0.x + b1.x + b2v.x + b3.x;
        ns[5] += b0.y + b1.y + b2v.y + b3.y;
        ns[6] += b0.z + b1.z + b2v.z + b3.z;
        ns[7] += b0.w + b1.w + b2v.w + b3.w;
    }

    float m[8];
    {
        float hid[16];
#pragma unroll
        for (int t = 0; t < 16; ++t) {
            float h = w[384 + t];
#pragma unroll
            for (int c = 0; c < 8; ++c) h += w[t * 24 + c] * (u[c] * deg);
#pragma unroll
            for (int c = 0; c < 8; ++c) h += w[t * 24 + 8 + c] * ns[c];
#pragma unroll
            for (int c = 0; c < 8; ++c) h += w[t * 24 + 16 + c] * eg;
            hid[t] = fmaxf(h, 0.f);
        }
#pragma unroll
        for (int o = 0; o < 8; ++o) {
            float v = w[528 + o];
#pragma unroll
            for (int t = 0; t < 16; ++t) v += w[400 + o * 16 + t] * hid[t];
            m[o] = v;
        }
    }

    float x[10];
#pragma unroll
    for (int c = 0; c < 8; ++c) x[c] = m[c];
    x[8] = rv;
    x[9] = nuv;

    float s[12];
#pragma unroll
    for (int c = 0; c < 12; ++c) s[c] = g_s[(size_t)node * 12 + c];

    float sn[12];
#pragma unroll
    for (int g = 0; g < 12; ++g) {
        float xr = w[1328 + g], xz = w[1328 + 12 + g], xn = w[1328 + 24 + g];
#pragma unroll
        for (int c = 0; c < 10; ++c) {
            float xv = x[c];
            xr += w[536 + g * 10 + c] * xv;
            xz += w[536 + (12 + g) * 10 + c] * xv;
            xn += w[536 + (24 + g) * 10 + c] * xv;
        }
        float hr = w[1364 + g], hz = w[1364 + 12 + g], hn = w[1364 + 24 + g];
#pragma unroll
        for (int c = 0; c < 12; ++c) {
            float sv = s[c];
            hr += w[896 + g * 12 + c] * sv;
            hz += w[896 + (12 + g) * 12 + c] * sv;
            hn += w[896 + (24 + g) * 12 + c] * sv;
        }
        float rg = sigf(xr + hr);
        float zg = sigf(xz + hz);
        float ng = tanhf(xn + rg * hn);
        sn[g] = (1.f - zg) * ng + zg * s[g];
    }
#pragma unroll
    for (int c = 0; c < 12; ++c) g_s[(size_t)node * 12 + c] = sn[c];

    float un[8];
#pragma unroll
    for (int o = 0; o < 8; ++o) {
        float v = w[1496 + o];
#pragma unroll
        for (int c = 0; c < 12; ++c) v += w[1400 + o * 12 + c] * sn[c];
        un[o] = v;
    }
    {
        float4* op = (float4*)(uout + (size_t)node * 8);
        op[0] = make_float4(un[0], un[1], un[2], un[3]);
        op[1] = make_float4(un[4], un[5], un[6], un[7]);
    }

    if (last) {
        float hid[16];
#pragma unroll
        for (int t = 0; t < 16; ++t) {
            float h = w[1640 + t];
#pragma unroll
            for (int c = 0; c < 8; ++c) h += w[1512 + t * 8 + c] * un[c];
            hid[t] = fmaxf(h, 0.f);
        }
        float l0 = w[1688], l1 = w[1689];
#pragma unroll
        for (int t = 0; t < 16; ++t) {
            l0 += w[1656 + t] * hid[t];
            l1 += w[1656 + 16 + t] * hid[t];
        }
        float mx = fmaxf(l0, l1);
        float e0 = expf(l0 - mx), e1 = expf(l1 - mx);
        float inv = 1.f / (e0 + e1);
        float p0 = e0 * inv, p1 = e1 * inv;
        const float q0 = -0.70710678118654752440f, q1 = 0.70710678118654752440f;
        float xh = p0 * q0 + p1 * q1;
        float nu = p0 * (q0 - xh) * (q0 - xh) + p1 * (q1 - xh) * (q1 - xh);
        nu = fmaxf(nu, 1e-10f);
        out[node]         = xh;
        out[NNODE + node] = nu;
    }
}

extern "C" void kernel_launch(void* const* d_in, const int* in_sizes, int n_in,
                              void* d_out, int out_size) {
    const float* y    = (const float*)d_in[0];
    const float* H    = (const float*)d_in[1];
    const float* r    = (const float*)d_in[2];
    const float* nur  = (const float*)d_in[3];
    const float* adj  = (const float*)d_in[4];
    const float* W1w  = (const float*)d_in[5];
    const float* W1b  = (const float*)d_in[6];
    const float* b1   = (const float*)d_in[7];
    const float* Wm1  = (const float*)d_in[8];
    const float* Wm1b = (const float*)d_in[9];
    const float* Wm2  = (const float*)d_in[10];
    const float* Wm2b = (const float*)d_in[11];
    const float* wih  = (const float*)d_in[12];
    const float* whh  = (const float*)d_in[13];
    const float* bih  = (const float*)d_in[14];
    const float* bhh  = (const float*)d_in[15];
    const float* W2   = (const float*)d_in[16];
    const float* W2b  = (const float*)d_in[17];
    const float* b2   = (const float*)d_in[18];
    const float* Wr1  = (const float*)d_in[19];
    const float* Wr1b = (const float*)d_in[20];
    const float* Wr2  = (const float*)d_in[21];
    const float* Wr2b = (const float*)d_in[22];
    float* out = (float*)d_out;

    const int GEMM_SMEM = 2 * BUFB;   // 61440 B
    cudaFuncSetAttribute(k_gemm, cudaFuncAttributeMaxDynamicSharedMemorySize, GEMM_SMEM);

    k_zero<<<(NNODE * 12 + 255) / 256, 256>>>();
    k_convcol<<<dim3(NB, NN / 128, 8), 128>>>(H, y);
    k_csr<<<NNODE / 8, 256>>>(adj, W1w, W1b, b1);
    k_gemm<<<dim3(8, 8, NB), 256, GEMM_SMEM>>>(H);
    k_node<<<NNODE / 128, 128>>>(r, nur, Wm1, Wm1b, Wm2, Wm2b, wih, whh, bih, bhh,
                                 W2, W2b, b2, Wr1, Wr1b, Wr2, Wr2b, 0, 0, out);
    k_node<<<NNODE / 128, 128>>>(r, nur, Wm1, Wm1b, Wm2, Wm2b, wih, whh, bih, bhh,
                                 W2, W2b, b2, Wr1, Wr1b, Wr2, Wr2b, 1, 1, out);
}

// round 9
// speedup vs baseline: 2.3153x; 1.0511x over previous
#include <cuda_runtime.h>
#include <cuda_fp16.h>
#include <stdint.h>
#include <math.h>

#define FULL 0xffffffffu

static const int NB    = 16;
static const int NN    = 1024;
static const int NNODE = NB * NN;   // 16384
static const int MAXN  = 192;

// -------- static device scratch (no allocations allowed) --------
__device__ float g_u[2][NNODE * 8 + 8];
__device__ float g_s[NNODE * 12];
__device__ float g_yhp[8 * NNODE];
__device__ float g_hhp[8 * NNODE];
__device__ float g_deg[NNODE];
__device__ float g_eg[NNODE];
__device__ int   g_nbru[NNODE * MAXN];
__device__ int   g_cnt[NNODE];
__device__ __half g_Hhi[(size_t)NB * NN * NN];
__device__ __half g_Hlo[(size_t)NB * NN * NN];
__device__ __half g_adjh[(size_t)NB * NN * NN];

__device__ __forceinline__ uint32_t sm_u32(const void* p) {
    uint32_t a;
    asm("{ .reg .u64 t; cvta.to.shared.u64 t, %1; cvt.u32.u64 %0, t; }"
        : "=r"(a) : "l"(p));
    return a;
}
__device__ __forceinline__ void cpasync16(uint32_t dst, const void* src) {
    asm volatile("cp.async.cg.shared.global [%0], [%1], 16;"
                 :: "r"(dst), "l"(src) : "memory");
}
__device__ __forceinline__ void ldsm4(uint32_t& r0, uint32_t& r1, uint32_t& r2,
                                      uint32_t& r3, uint32_t a) {
    asm volatile("ldmatrix.sync.aligned.m8n8.x4.shared.b16 {%0,%1,%2,%3}, [%4];"
                 : "=r"(r0), "=r"(r1), "=r"(r2), "=r"(r3) : "r"(a));
}
__device__ __forceinline__ void mma16816(float* c, uint32_t a0, uint32_t a1,
                                         uint32_t a2, uint32_t a3,
                                         uint32_t b0, uint32_t b1) {
    asm volatile(
        "mma.sync.aligned.m16n8k16.row.col.f32.f16.f16.f32 "
        "{%0,%1,%2,%3}, {%4,%5,%6,%7}, {%8,%9}, {%0,%1,%2,%3};"
        : "+f"(c[0]), "+f"(c[1]), "+f"(c[2]), "+f"(c[3])
        : "r"(a0), "r"(a1), "r"(a2), "r"(a3), "r"(b0), "r"(b1));
}

// -------- one pass over H: yh/hh partials + fp16 hi/lo split --------
__global__ void k_convcol(const float* __restrict__ H, const float* __restrict__ y) {
    __shared__ float sy[128];
    int b = blockIdx.x, j = blockIdx.y * 128 + threadIdx.x, k0 = blockIdx.z * 128;
    sy[threadIdx.x] = y[b * NN + k0 + threadIdx.x];
    __syncthreads();
    const float* Hb = H + ((size_t)b * NN + k0) * NN + j;
    __half* hi = g_Hhi + ((size_t)b * NN + k0) * NN + j;
    __half* lo = g_Hlo + ((size_t)b * NN + k0) * NN + j;
    float yh = 0.f, hh = 0.f;
#pragma unroll 4
    for (int i = 0; i < 128; ++i) {
        float h = Hb[(size_t)i * NN];
        __half hb = __float2half(h);
        hi[(size_t)i * NN] = hb;
        lo[(size_t)i * NN] = __float2half(h - __half2float(hb));
        yh += sy[i] * h;
        hh += h * h;
    }
    int node = b * NN + j;
    g_yhp[blockIdx.z * NNODE + node] = yh;
    g_hhp[blockIdx.z * NNODE + node] = hh;
}

// -------- adj pass: neighbor lists + deg + fp16 adj + u0 + zero-init --------
__global__ void k_csr(const float* __restrict__ adj, const float* __restrict__ W1w,
                      const float* __restrict__ W1b, const float* __restrict__ b1) {
    int row  = blockIdx.x * (blockDim.x >> 5) + (threadIdx.x >> 5);
    int lane = threadIdx.x & 31;
    const float* ar = adj + (size_t)row * NN;
    __half* ah = g_adjh + (size_t)row * NN;
    const __half ONE = __float2half(1.f), ZERO = __float2half(0.f);
    int base = row * MAXN;
    int boff = (row >> 10) << 10;
    int cnt  = 0;
    for (int c = 0; c < NN; c += 32) {
        float a = ar[c + lane];
        ah[c + lane] = (a != 0.f) ? ONE : ZERO;
        unsigned m = __ballot_sync(FULL, a != 0.f);
        if (a != 0.f) {
            int pos = cnt + __popc(m & ((1u << lane) - 1u));
            if (pos < MAXN) g_nbru[base + pos] = (boff + c + lane) * 8;
        }
        cnt += __popc(m);
    }
    int cntc = cnt < MAXN ? cnt : MAXN;
    int cntp = (cntc + 3) & ~3;
    if (lane < cntp - cntc) g_nbru[base + cntc + lane] = NNODE * 8;  // zero u row
    if (lane == 0) {
        g_cnt[row] = cntc;
        g_deg[row] = (float)cnt;
        g_eg[row]  = 0.f;
    }
    if (lane < 12) g_s[(size_t)row * 12 + lane] = 0.f;
    if (row == 0 && lane < 8) { g_u[0][NNODE * 8 + lane] = 0.f; g_u[1][NNODE * 8 + lane] = 0.f; }
    if (lane < 8) {
        float yh = 0.f, hh = 0.f;
#pragma unroll
        for (int z = 0; z < 8; ++z) {
            yh += g_yhp[z * NNODE + row];
            hh += g_hhp[z * NNODE + row];
        }
        g_u[0][(size_t)row * 8 + lane] =
            W1w[2 * lane] * yh + W1w[2 * lane + 1] * hh + W1b[lane] + b1[lane];
    }
}

// -------- eg via mma.sync: T = (Hhi+Hlo) @ adj^T, eg_i = sum_k H[k,i]*T[k,i] --
// CTA = 128x128 tile (m = k-rows, n = i-cols). 8 warps as 2x4. K in 32-wide
// chunks, 3-stage cp.async pipeline, ONE syncthreads per chunk, ldmatrix frags.
static const int TSTRIDE = 80;              // bytes per tile row (40 halves)
static const int TILEB   = 128 * TSTRIDE;   // 10240 B per tile
static const int STAGEB  = 3 * TILEB;       // Ahi, Alo, B per stage

__global__ void __launch_bounds__(256, 2) k_gemm(const float* __restrict__ H) {
    extern __shared__ __align__(16) char smb[];
    const int tid = threadIdx.x, wid = tid >> 5, lane = tid & 31;
    const int g = lane >> 2, t = lane & 3;
    const int b = blockIdx.z;
    const int i0 = blockIdx.x * 128, k0 = blockIdx.y * 128;
    const int wm = wid & 1, wn = wid >> 1;

    const __half* Ahi = g_Hhi  + ((size_t)b * NN + k0) * NN;
    const __half* Alo = g_Hlo  + ((size_t)b * NN + k0) * NN;
    const __half* Bad = g_adjh + ((size_t)b * NN + i0) * NN;
    const uint32_t sbase = sm_u32(smb);

    // ldmatrix lane-address components (constant per thread)
    const int arow = (lane & 7) + ((lane >> 3) & 1) * 8;   // A: row offset
    const int acol = (lane >> 4) * 16;                     // A: col byte offset
    const int brow = (lane & 7) + (lane >> 4) * 8;         // B: row offset
    const int bcol = ((lane >> 3) & 1) * 16;               // B: col byte offset

    float acc[4][4][4];
#pragma unroll
    for (int a = 0; a < 4; ++a)
#pragma unroll
        for (int n = 0; n < 4; ++n)
#pragma unroll
            for (int r = 0; r < 4; ++r) acc[a][n][r] = 0.f;

    auto issue = [&](int c) {
        int j0 = c * 32;
        uint32_t tb = sbase + (c % 3) * STAGEB;
#pragma unroll
        for (int q = 0; q < 2; ++q) {
            int idx = tid + q * 256;
            int row = idx >> 2, quad = idx & 3;
            uint32_t so = tb + row * TSTRIDE + quad * 16;
            cpasync16(so,             Ahi + (size_t)row * NN + j0 + quad * 8);
            cpasync16(so + TILEB,     Alo + (size_t)row * NN + j0 + quad * 8);
            cpasync16(so + 2 * TILEB, Bad + (size_t)row * NN + j0 + quad * 8);
        }
        asm volatile("cp.async.commit_group;" ::: "memory");
    };

    issue(0);
    issue(1);
    for (int c = 0; c < 32; ++c) {
        if (c < 31) asm volatile("cp.async.wait_group 1;" ::: "memory");
        else        asm volatile("cp.async.wait_group 0;" ::: "memory");
        __syncthreads();
        if (c < 30) issue(c + 2);
        uint32_t sA = sbase + (c % 3) * STAGEB;
        uint32_t sL = sA + TILEB, sB = sA + 2 * TILEB;
#pragma unroll
        for (int ks = 0; ks < 2; ++ks) {
            uint32_t bfr[4][2];
            ldsm4(bfr[0][0], bfr[0][1], bfr[1][0], bfr[1][1],
                  sB + (wn * 32 + brow) * TSTRIDE + ks * 32 + bcol);
            ldsm4(bfr[2][0], bfr[2][1], bfr[3][0], bfr[3][1],
                  sB + (wn * 32 + 16 + brow) * TSTRIDE + ks * 32 + bcol);
#pragma unroll
            for (int sp = 0; sp < 2; ++sp) {
                uint32_t sa = sp ? sL : sA;
#pragma unroll
                for (int mi = 0; mi < 4; ++mi) {
                    uint32_t a0, a1, a2, a3;
                    ldsm4(a0, a1, a2, a3,
                          sa + (wm * 64 + mi * 16 + arow) * TSTRIDE + ks * 32 + acol);
#pragma unroll
                    for (int ni = 0; ni < 4; ++ni)
                        mma16816(acc[mi][ni], a0, a1, a2, a3, bfr[ni][0], bfr[ni][1]);
                }
            }
        }
    }

    // --- epilogue: eg[i0+n] += sum_m H[k0+m, i0+n] * D[m, n] ---
    const float* Hb = H + ((size_t)b * NN + k0) * NN + i0;
#pragma unroll
    for (int ni = 0; ni < 4; ++ni) {
        int col = wn * 32 + ni * 8 + 2 * t;
        float p0 = 0.f, p1 = 0.f;
#pragma unroll
        for (int mi = 0; mi < 4; ++mi) {
            int m = wm * 64 + mi * 16;
            float2 h0 = *(const float2*)(Hb + (size_t)(m + g) * NN + col);
            float2 h1 = *(const float2*)(Hb + (size_t)(m + g + 8) * NN + col);
            p0 += acc[mi][ni][0] * h0.x + acc[mi][ni][2] * h1.x;
            p1 += acc[mi][ni][1] * h0.y + acc[mi][ni][3] * h1.y;
        }
#pragma unroll
        for (int o = 4; o < 32; o <<= 1) {
            p0 += __shfl_xor_sync(FULL, p0, o);
            p1 += __shfl_xor_sync(FULL, p1, o);
        }
        if (g == 0) {
            atomicAdd(&g_eg[b * NN + i0 + col], p0);
            atomicAdd(&g_eg[b * NN + i0 + col + 1], p1);
        }
    }
}

__device__ __forceinline__ float sigf(float x) { return 1.f / (1.f + expf(-x)); }

// -------- fused per-node: msg MLP + GRU + W2 (+ readout on last iter) --------
__global__ void k_node(const float* __restrict__ r, const float* __restrict__ nur,
                       const float* __restrict__ Wm1, const float* __restrict__ Wm1b,
                       const float* __restrict__ Wm2, const float* __restrict__ Wm2b,
                       const float* __restrict__ wih, const float* __restrict__ whh,
                       const float* __restrict__ bih, const float* __restrict__ bhh,
                       const float* __restrict__ W2,  const float* __restrict__ W2b,
                       const float* __restrict__ b2,
                       const float* __restrict__ Wr1, const float* __restrict__ Wr1b,
                       const float* __restrict__ Wr2, const float* __restrict__ Wr2b,
                       int bufin, int last, float* __restrict__ out) {
    __shared__ float w[1690];
    {
        int t = threadIdx.x;
        for (int i = t; i < 384; i += blockDim.x) w[i]        = Wm1[i];
        for (int i = t; i < 16;  i += blockDim.x) w[384 + i]  = Wm1b[i];
        for (int i = t; i < 128; i += blockDim.x) w[400 + i]  = Wm2[i];
        for (int i = t; i < 8;   i += blockDim.x) w[528 + i]  = Wm2b[i];
        for (int i = t; i < 360; i += blockDim.x) w[536 + i]  = wih[i];
        for (int i = t; i < 432; i += blockDim.x) w[896 + i]  = whh[i];
        for (int i = t; i < 36;  i += blockDim.x) w[1328 + i] = bih[i];
        for (int i = t; i < 36;  i += blockDim.x) w[1364 + i] = bhh[i];
        for (int i = t; i < 96;  i += blockDim.x) w[1400 + i] = W2[i];
        for (int i = t; i < 8;   i += blockDim.x) w[1496 + i] = W2b[i] + b2[i];
        for (int i = t; i < 128; i += blockDim.x) w[1512 + i] = Wr1[i];
        for (int i = t; i < 16;  i += blockDim.x) w[1640 + i] = Wr1b[i];
        for (int i = t; i < 32;  i += blockDim.x) w[1656 + i] = Wr2[i];
        for (int i = t; i < 2;   i += blockDim.x) w[1688 + i] = Wr2b[i];
    }
    __syncthreads();
    int node = blockIdx.x * blockDim.x + threadIdx.x;
    const float* uin = g_u[bufin];
    float* uout = g_u[bufin ^ 1];

    float rv  = r[node];
    float nuv = fmaxf(nur[node], 1e-10f);
    float deg = g_deg[node], eg = g_eg[node];

    float u[8];
    {
        const float4* up = (const float4*)(uin + (size_t)node * 8);
        float4 a = up[0], b4 = up[1];
        u[0] = a.x; u[1] = a.y; u[2] = a.z; u[3] = a.w;
        u[4] = b4.x; u[5] = b4.y; u[6] = b4.z; u[7] = b4.w;
    }

    float ns[8] = {0, 0, 0, 0, 0, 0, 0, 0};
    int nq = ((g_cnt[node] + 3) & ~3) >> 2;
    const int4* off = (const int4*)&g_nbru[node * MAXN];
#pragma unroll 2
    for (int q = 0; q < nq; ++q) {
        int4 o = off[q];
        const float4* p0 = (const float4*)(uin + o.x);
        const float4* p1 = (const float4*)(uin + o.y);
        const float4* p2 = (const float4*)(uin + o.z);
        const float4* p3 = (const float4*)(uin + o.w);
        float4 a0 = p0[0], b0 = p0[1];
        float4 a1 = p1[0], b1 = p1[1];
        float4 a2 = p2[0], b2v = p2[1];
        float4 a3 = p3[0], b3 = p3[1];
        ns[0] += a0.x + a1.x + a2.x + a3.x;
        ns[1] += a0.y + a1.y + a2.y + a3.y;
        ns[2] += a0.z + a1.z + a2.z + a3.z;
        ns[3] += a0.w + a1.w + a2.w + a3.w;
        ns[4] += b0.x + b1.x + b2v.x + b3.x;
        ns[5] += b0.y + b1.y + b2v.y + b3.y;
        ns[6] += b0.z + b1.z + b2v.z + b3.z;
        ns[7] += b0.w + b1.w + b2v.w + b3.w;
    }

    float m[8];
    {
        float hid[16];
#pragma unroll
        for (int t = 0; t < 16; ++t) {
            float h = w[384 + t];
#pragma unroll
            for (int c = 0; c < 8; ++c) h += w[t * 24 + c] * (u[c] * deg);
#pragma unroll
            for (int c = 0; c < 8; ++c) h += w[t * 24 + 8 + c] * ns[c];
#pragma unroll
            for (int c = 0; c < 8; ++c) h += w[t * 24 + 16 + c] * eg;
            hid[t] = fmaxf(h, 0.f);
        }
#pragma unroll
        for (int o = 0; o < 8; ++o) {
            float v = w[528 + o];
#pragma unroll
            for (int t = 0; t < 16; ++t) v += w[400 + o * 16 + t] * hid[t];
            m[o] = v;
        }
    }

    float x[10];
#pragma unroll
    for (int c = 0; c < 8; ++c) x[c] = m[c];
    x[8] = rv;
    x[9] = nuv;

    float s[12];
#pragma unroll
    for (int c = 0; c < 12; ++c) s[c] = g_s[(size_t)node * 12 + c];

    float sn[12];
#pragma unroll
    for (int g = 0; g < 12; ++g) {
        float xr = w[1328 + g], xz = w[1328 + 12 + g], xn = w[1328 + 24 + g];
#pragma unroll
        for (int c = 0; c < 10; ++c) {
            float xv = x[c];
            xr += w[536 + g * 10 + c] * xv;
            xz += w[536 + (12 + g) * 10 + c] * xv;
            xn += w[536 + (24 + g) * 10 + c] * xv;
        }
        float hr = w[1364 + g], hz = w[1364 + 12 + g], hn = w[1364 + 24 + g];
#pragma unroll
        for (int c = 0; c < 12; ++c) {
            float sv = s[c];
            hr += w[896 + g * 12 + c] * sv;
            hz += w[896 + (12 + g) * 12 + c] * sv;
            hn += w[896 + (24 + g) * 12 + c] * sv;
        }
        float rg = sigf(xr + hr);
        float zg = sigf(xz + hz);
        float ng = tanhf(xn + rg * hn);
        sn[g] = (1.f - zg) * ng + zg * s[g];
    }
#pragma unroll
    for (int c = 0; c < 12; ++c) g_s[(size_t)node * 12 + c] = sn[c];

    float un[8];
#pragma unroll
    for (int o = 0; o < 8; ++o) {
        float v = w[1496 + o];
#pragma unroll
        for (int c = 0; c < 12; ++c) v += w[1400 + o * 12 + c] * sn[c];
        un[o] = v;
    }
    {
        float4* op = (float4*)(uout + (size_t)node * 8);
        op[0] = make_float4(un[0], un[1], un[2], un[3]);
        op[1] = make_float4(un[4], un[5], un[6], un[7]);
    }

    if (last) {
        float hid[16];
#pragma unroll
        for (int t = 0; t < 16; ++t) {
            float h = w[1640 + t];
#pragma unroll
            for (int c = 0; c < 8; ++c) h += w[1512 + t * 8 + c] * un[c];
            hid[t] = fmaxf(h, 0.f);
        }
        float l0 = w[1688], l1 = w[1689];
#pragma unroll
        for (int t = 0; t < 16; ++t) {
            l0 += w[1656 + t] * hid[t];
            l1 += w[1656 + 16 + t] * hid[t];
        }
        float mx = fmaxf(l0, l1);
        float e0 = expf(l0 - mx), e1 = expf(l1 - mx);
        float inv = 1.f / (e0 + e1);
        float p0 = e0 * inv, p1 = e1 * inv;
        const float q0 = -0.70710678118654752440f, q1 = 0.70710678118654752440f;
        float xh = p0 * q0 + p1 * q1;
        float nu = p0 * (q0 - xh) * (q0 - xh) + p1 * (q1 - xh) * (q1 - xh);
        nu = fmaxf(nu, 1e-10f);
        out[node]         = xh;
        out[NNODE + node] = nu;
    }
}

extern "C" void kernel_launch(void* const* d_in, const int* in_sizes, int n_in,
                              void* d_out, int out_size) {
    const float* y    = (const float*)d_in[0];
    const float* H    = (const float*)d_in[1];
    const float* r    = (const float*)d_in[2];
    const float* nur  = (const float*)d_in[3];
    const float* adj  = (const float*)d_in[4];
    const float* W1w  = (const float*)d_in[5];
    const float* W1b  = (const float*)d_in[6];
    const float* b1   = (const float*)d_in[7];
    const float* Wm1  = (const float*)d_in[8];
    const float* Wm1b = (const float*)d_in[9];
    const float* Wm2  = (const float*)d_in[10];
    const float* Wm2b = (const float*)d_in[11];
    const float* wih  = (const float*)d_in[12];
    const float* whh  = (const float*)d_in[13];
    const float* bih  = (const float*)d_in[14];
    const float* bhh  = (const float*)d_in[15];
    const float* W2   = (const float*)d_in[16];
    const float* W2b  = (const float*)d_in[17];
    const float* b2   = (const float*)d_in[18];
    const float* Wr1  = (const float*)d_in[19];
    const float* Wr1b = (const float*)d_in[20];
    const float* Wr2  = (const float*)d_in[21];
    const float* Wr2b = (const float*)d_in[22];
    float* out = (float*)d_out;

    const int GEMM_SMEM = 3 * STAGEB;   // 92160 B
    cudaFuncSetAttribute(k_gemm, cudaFuncAttributeMaxDynamicSharedMemorySize, GEMM_SMEM);

    k_convcol<<<dim3(NB, NN / 128, 8), 128>>>(H, y);
    k_csr<<<NNODE / 8, 256>>>(adj, W1w, W1b, b1);
    k_gemm<<<dim3(8, 8, NB), 256, GEMM_SMEM>>>(H);
    k_node<<<NNODE / 128, 128>>>(r, nur, Wm1, Wm1b, Wm2, Wm2b, wih, whh, bih, bhh,
                                 W2, W2b, b2, Wr1, Wr1b, Wr2, Wr2b, 0, 0, out);
    k_node<<<NNODE / 128, 128>>>(r, nur, Wm1, Wm1b, Wm2, Wm2b, wih, whh, bih, bhh,
                                 W2, W2b, b2, Wr1, Wr1b, Wr2, Wr2b, 1, 1, out);
}

// round 10
// speedup vs baseline: 2.3379x; 1.0097x over previous
#include <cuda_runtime.h>
#include <cuda_fp16.h>
#include <stdint.h>
#include <math.h>

#define FULL 0xffffffffu

static const int NB    = 16;
static const int NN    = 1024;
static const int NNODE = NB * NN;   // 16384
static const int MAXN  = 192;

// -------- static device scratch (no allocations allowed) --------
__device__ float g_u[2][NNODE * 8 + 8];
__device__ float g_s[NNODE * 12];
__device__ float g_yhp[8 * NNODE];
__device__ float g_hhp[8 * NNODE];
__device__ float g_deg[NNODE];
__device__ float g_eg[NNODE];
__device__ int   g_nbru[NNODE * MAXN];
__device__ int   g_cnt[NNODE];
__device__ __half g_Hhi[(size_t)NB * NN * NN];
__device__ __half g_Hlo[(size_t)NB * NN * NN];
__device__ __half g_adjh[(size_t)NB * NN * NN];

__device__ __forceinline__ uint32_t sm_u32(const void* p) {
    uint32_t a;
    asm("{ .reg .u64 t; cvta.to.shared.u64 t, %1; cvt.u32.u64 %0, t; }"
        : "=r"(a) : "l"(p));
    return a;
}
__device__ __forceinline__ void cpasync16(uint32_t dst, const void* src) {
    asm volatile("cp.async.cg.shared.global [%0], [%1], 16;"
                 :: "r"(dst), "l"(src) : "memory");
}
__device__ __forceinline__ void ldsm4(uint32_t& r0, uint32_t& r1, uint32_t& r2,
                                      uint32_t& r3, uint32_t a) {
    asm volatile("ldmatrix.sync.aligned.m8n8.x4.shared.b16 {%0,%1,%2,%3}, [%4];"
                 : "=r"(r0), "=r"(r1), "=r"(r2), "=r"(r3) : "r"(a));
}
__device__ __forceinline__ void mma16816(float* c, uint32_t a0, uint32_t a1,
                                         uint32_t a2, uint32_t a3,
                                         uint32_t b0, uint32_t b1) {
    asm volatile(
        "mma.sync.aligned.m16n8k16.row.col.f32.f16.f16.f32 "
        "{%0,%1,%2,%3}, {%4,%5,%6,%7}, {%8,%9}, {%0,%1,%2,%3};"
        : "+f"(c[0]), "+f"(c[1]), "+f"(c[2]), "+f"(c[3])
        : "r"(a0), "r"(a1), "r"(a2), "r"(a3), "r"(b0), "r"(b1));
}

// -------- one pass over H: yh/hh partials + fp16 hi/lo split --------
__global__ void k_convcol(const float* __restrict__ H, const float* __restrict__ y) {
    __shared__ float sy[128];
    int b = blockIdx.x, j = blockIdx.y * 128 + threadIdx.x, k0 = blockIdx.z * 128;
    sy[threadIdx.x] = y[b * NN + k0 + threadIdx.x];
    __syncthreads();
    const float* Hb = H + ((size_t)b * NN + k0) * NN + j;
    __half* hi = g_Hhi + ((size_t)b * NN + k0) * NN + j;
    __half* lo = g_Hlo + ((size_t)b * NN + k0) * NN + j;
    float yh = 0.f, hh = 0.f;
#pragma unroll 4
    for (int i = 0; i < 128; ++i) {
        float h = Hb[(size_t)i * NN];
        __half hb = __float2half(h);
        hi[(size_t)i * NN] = hb;
        lo[(size_t)i * NN] = __float2half(h - __half2float(hb));
        yh += sy[i] * h;
        hh += h * h;
    }
    int node = b * NN + j;
    g_yhp[blockIdx.z * NNODE + node] = yh;
    g_hhp[blockIdx.z * NNODE + node] = hh;
}

// -------- adj pass: neighbor lists + deg + fp16 adj + zero-init --------
__global__ void k_csr(const float* __restrict__ adj) {
    int row  = blockIdx.x * (blockDim.x >> 5) + (threadIdx.x >> 5);
    int lane = threadIdx.x & 31;
    const float* ar = adj + (size_t)row * NN;
    __half* ah = g_adjh + (size_t)row * NN;
    const __half ONE = __float2half(1.f), ZERO = __float2half(0.f);
    int base = row * MAXN;
    int boff = (row >> 10) << 10;
    int cnt  = 0;
    for (int c = 0; c < NN; c += 32) {
        float a = ar[c + lane];
        ah[c + lane] = (a != 0.f) ? ONE : ZERO;
        unsigned m = __ballot_sync(FULL, a != 0.f);
        if (a != 0.f) {
            int pos = cnt + __popc(m & ((1u << lane) - 1u));
            if (pos < MAXN) g_nbru[base + pos] = (boff + c + lane) * 8;
        }
        cnt += __popc(m);
    }
    int cntc = cnt < MAXN ? cnt : MAXN;
    int cntp = (cntc + 3) & ~3;
    if (lane < cntp - cntc) g_nbru[base + cntc + lane] = NNODE * 8;  // zero u row
    if (lane == 0) {
        g_cnt[row] = cntc;
        g_deg[row] = (float)cnt;
        g_eg[row]  = 0.f;
    }
    if (lane < 12) g_s[(size_t)row * 12 + lane] = 0.f;
    if (row == 0 && lane < 8) { g_u[0][NNODE * 8 + lane] = 0.f; g_u[1][NNODE * 8 + lane] = 0.f; }
}

// -------- eg via mma.sync: T = (Hhi+Hlo) @ adj^T, eg_i = sum_k H[k,i]*T[k,i] --
static const int TSTRIDE = 80;              // bytes per tile row (40 halves)
static const int TILEB   = 128 * TSTRIDE;   // 10240 B per tile
static const int STAGEB  = 3 * TILEB;       // Ahi, Alo, B per stage

__global__ void __launch_bounds__(256, 2) k_gemm(const float* __restrict__ H,
                                                 const float* __restrict__ W1w,
                                                 const float* __restrict__ W1b,
                                                 const float* __restrict__ b1) {
    extern __shared__ __align__(16) char smb[];
    const int tid = threadIdx.x, wid = tid >> 5, lane = tid & 31;
    const int g = lane >> 2, t = lane & 3;
    const int b = blockIdx.z;
    const int i0 = blockIdx.x * 128, k0 = blockIdx.y * 128;
    const int wm = wid & 1, wn = wid >> 1;

    // u0 = W1([yh,hh]) finalize on the 128 blocks with blockIdx.y==0
    if (blockIdx.y == 0 && tid < 128) {
        int node = (b * 8 + blockIdx.x) * 128 + tid;
        float yh = 0.f, hh = 0.f;
#pragma unroll
        for (int z = 0; z < 8; ++z) {
            yh += g_yhp[z * NNODE + node];
            hh += g_hhp[z * NNODE + node];
        }
        float* up = &g_u[0][(size_t)node * 8];
#pragma unroll
        for (int c = 0; c < 8; ++c)
            up[c] = W1w[2 * c] * yh + W1w[2 * c + 1] * hh + W1b[c] + b1[c];
    }

    const __half* Ahi = g_Hhi  + ((size_t)b * NN + k0) * NN;
    const __half* Alo = g_Hlo  + ((size_t)b * NN + k0) * NN;
    const __half* Bad = g_adjh + ((size_t)b * NN + i0) * NN;
    const uint32_t sbase = sm_u32(smb);

    const int arow = (lane & 7) + ((lane >> 3) & 1) * 8;
    const int acol = (lane >> 4) * 16;
    const int brow = (lane & 7) + (lane >> 4) * 8;
    const int bcol = ((lane >> 3) & 1) * 16;

    float acc[4][4][4];
#pragma unroll
    for (int a = 0; a < 4; ++a)
#pragma unroll
        for (int n = 0; n < 4; ++n)
#pragma unroll
            for (int r = 0; r < 4; ++r) acc[a][n][r] = 0.f;

    auto issue = [&](int c) {
        int j0 = c * 32;
        uint32_t tb = sbase + (c % 3) * STAGEB;
#pragma unroll
        for (int q = 0; q < 2; ++q) {
            int idx = tid + q * 256;
            int row = idx >> 2, quad = idx & 3;
            uint32_t so = tb + row * TSTRIDE + quad * 16;
            cpasync16(so,             Ahi + (size_t)row * NN + j0 + quad * 8);
            cpasync16(so + TILEB,     Alo + (size_t)row * NN + j0 + quad * 8);
            cpasync16(so + 2 * TILEB, Bad + (size_t)row * NN + j0 + quad * 8);
        }
        asm volatile("cp.async.commit_group;" ::: "memory");
    };

    issue(0);
    issue(1);
    for (int c = 0; c < 32; ++c) {
        if (c < 31) asm volatile("cp.async.wait_group 1;" ::: "memory");
        else        asm volatile("cp.async.wait_group 0;" ::: "memory");
        __syncthreads();
        if (c < 30) issue(c + 2);
        uint32_t sA = sbase + (c % 3) * STAGEB;
        uint32_t sL = sA + TILEB, sB = sA + 2 * TILEB;
#pragma unroll
        for (int ks = 0; ks < 2; ++ks) {
            uint32_t bfr[4][2];
            ldsm4(bfr[0][0], bfr[0][1], bfr[1][0], bfr[1][1],
                  sB + (wn * 32 + brow) * TSTRIDE + ks * 32 + bcol);
            ldsm4(bfr[2][0], bfr[2][1], bfr[3][0], bfr[3][1],
                  sB + (wn * 32 + 16 + brow) * TSTRIDE + ks * 32 + bcol);
#pragma unroll
            for (int sp = 0; sp < 2; ++sp) {
                uint32_t sa = sp ? sL : sA;
#pragma unroll
                for (int mi = 0; mi < 4; ++mi) {
                    uint32_t a0, a1, a2, a3;
                    ldsm4(a0, a1, a2, a3,
                          sa + (wm * 64 + mi * 16 + arow) * TSTRIDE + ks * 32 + acol);
#pragma unroll
                    for (int ni = 0; ni < 4; ++ni)
                        mma16816(acc[mi][ni], a0, a1, a2, a3, bfr[ni][0], bfr[ni][1]);
                }
            }
        }
    }

    const float* Hb = H + ((size_t)b * NN + k0) * NN + i0;
#pragma unroll
    for (int ni = 0; ni < 4; ++ni) {
        int col = wn * 32 + ni * 8 + 2 * t;
        float p0 = 0.f, p1 = 0.f;
#pragma unroll
        for (int mi = 0; mi < 4; ++mi) {
            int m = wm * 64 + mi * 16;
            float2 h0 = *(const float2*)(Hb + (size_t)(m + g) * NN + col);
            float2 h1 = *(const float2*)(Hb + (size_t)(m + g + 8) * NN + col);
            p0 += acc[mi][ni][0] * h0.x + acc[mi][ni][2] * h1.x;
            p1 += acc[mi][ni][1] * h0.y + acc[mi][ni][3] * h1.y;
        }
#pragma unroll
        for (int o = 4; o < 32; o <<= 1) {
            p0 += __shfl_xor_sync(FULL, p0, o);
            p1 += __shfl_xor_sync(FULL, p1, o);
        }
        if (g == 0) {
            atomicAdd(&g_eg[b * NN + i0 + col], p0);
            atomicAdd(&g_eg[b * NN + i0 + col + 1], p1);
        }
    }
}

__device__ __forceinline__ float sigf(float x) { return 1.f / (1.f + expf(-x)); }

// -------- fused per-node: 4-thread gather + msg MLP + GRU + W2 (+ readout) --
// blockDim 128 = 32 nodes x 4 gather lanes. Lane 0 of each quad does compute.
__global__ void k_node(const float* __restrict__ r, const float* __restrict__ nur,
                       const float* __restrict__ Wm1, const float* __restrict__ Wm1b,
                       const float* __restrict__ Wm2, const float* __restrict__ Wm2b,
                       const float* __restrict__ wih, const float* __restrict__ whh,
                       const float* __restrict__ bih, const float* __restrict__ bhh,
                       const float* __restrict__ W2,  const float* __restrict__ W2b,
                       const float* __restrict__ b2,
                       const float* __restrict__ Wr1, const float* __restrict__ Wr1b,
                       const float* __restrict__ Wr2, const float* __restrict__ Wr2b,
                       int bufin, int last, float* __restrict__ out) {
    __shared__ float w[1690];
    {
        int t = threadIdx.x;
        for (int i = t; i < 384; i += blockDim.x) w[i]        = Wm1[i];
        for (int i = t; i < 16;  i += blockDim.x) w[384 + i]  = Wm1b[i];
        for (int i = t; i < 128; i += blockDim.x) w[400 + i]  = Wm2[i];
        for (int i = t; i < 8;   i += blockDim.x) w[528 + i]  = Wm2b[i];
        for (int i = t; i < 360; i += blockDim.x) w[536 + i]  = wih[i];
        for (int i = t; i < 432; i += blockDim.x) w[896 + i]  = whh[i];
        for (int i = t; i < 36;  i += blockDim.x) w[1328 + i] = bih[i];
        for (int i = t; i < 36;  i += blockDim.x) w[1364 + i] = bhh[i];
        for (int i = t; i < 96;  i += blockDim.x) w[1400 + i] = W2[i];
        for (int i = t; i < 8;   i += blockDim.x) w[1496 + i] = W2b[i] + b2[i];
        for (int i = t; i < 128; i += blockDim.x) w[1512 + i] = Wr1[i];
        for (int i = t; i < 16;  i += blockDim.x) w[1640 + i] = Wr1b[i];
        for (int i = t; i < 32;  i += blockDim.x) w[1656 + i] = Wr2[i];
        for (int i = t; i < 2;   i += blockDim.x) w[1688 + i] = Wr2b[i];
    }
    __syncthreads();
    int q    = threadIdx.x & 3;
    int node = blockIdx.x * 32 + (threadIdx.x >> 2);
    const float* uin = g_u[bufin];
    float* uout = g_u[bufin ^ 1];

    // 4-lane cooperative neighbor gather
    float ns[8] = {0, 0, 0, 0, 0, 0, 0, 0};
    int nq = ((g_cnt[node] + 3) & ~3) >> 2;
    const int4* off = (const int4*)&g_nbru[node * MAXN];
    for (int i = q; i < nq; i += 4) {
        int4 o = off[i];
        const float4* p0 = (const float4*)(uin + o.x);
        const float4* p1 = (const float4*)(uin + o.y);
        const float4* p2 = (const float4*)(uin + o.z);
        const float4* p3 = (const float4*)(uin + o.w);
        float4 a0 = p0[0], b0 = p0[1];
        float4 a1 = p1[0], b1 = p1[1];
        float4 a2 = p2[0], b2v = p2[1];
        float4 a3 = p3[0], b3 = p3[1];
        ns[0] += a0.x + a1.x + a2.x + a3.x;
        ns[1] += a0.y + a1.y + a2.y + a3.y;
        ns[2] += a0.z + a1.z + a2.z + a3.z;
        ns[3] += a0.w + a1.w + a2.w + a3.w;
        ns[4] += b0.x + b1.x + b2v.x + b3.x;
        ns[5] += b0.y + b1.y + b2v.y + b3.y;
        ns[6] += b0.z + b1.z + b2v.z + b3.z;
        ns[7] += b0.w + b1.w + b2v.w + b3.w;
    }
#pragma unroll
    for (int c = 0; c < 8; ++c) {
        ns[c] += __shfl_xor_sync(FULL, ns[c], 1);
        ns[c] += __shfl_xor_sync(FULL, ns[c], 2);
    }
    if (q != 0) return;   // no syncthreads below this point

    float rv  = r[node];
    float nuv = fmaxf(nur[node], 1e-10f);
    float deg = g_deg[node], eg = g_eg[node];

    float u[8];
    {
        const float4* up = (const float4*)(uin + (size_t)node * 8);
        float4 a = up[0], b4 = up[1];
        u[0] = a.x; u[1] = a.y; u[2] = a.z; u[3] = a.w;
        u[4] = b4.x; u[5] = b4.y; u[6] = b4.z; u[7] = b4.w;
    }

    float m[8];
    {
        float hid[16];
#pragma unroll
        for (int t = 0; t < 16; ++t) {
            float h = w[384 + t];
#pragma unroll
            for (int c = 0; c < 8; ++c) h += w[t * 24 + c] * (u[c] * deg);
#pragma unroll
            for (int c = 0; c < 8; ++c) h += w[t * 24 + 8 + c] * ns[c];
#pragma unroll
            for (int c = 0; c < 8; ++c) h += w[t * 24 + 16 + c] * eg;
            hid[t] = fmaxf(h, 0.f);
        }
#pragma unroll
        for (int o = 0; o < 8; ++o) {
            float v = w[528 + o];
#pragma unroll
            for (int t = 0; t < 16; ++t) v += w[400 + o * 16 + t] * hid[t];
            m[o] = v;
        }
    }

    float x[10];
#pragma unroll
    for (int c = 0; c < 8; ++c) x[c] = m[c];
    x[8] = rv;
    x[9] = nuv;

    float s[12];
#pragma unroll
    for (int c = 0; c < 12; ++c) s[c] = g_s[(size_t)node * 12 + c];

    float sn[12];
#pragma unroll
    for (int g = 0; g < 12; ++g) {
        float xr = w[1328 + g], xz = w[1328 + 12 + g], xn = w[1328 + 24 + g];
#pragma unroll
        for (int c = 0; c < 10; ++c) {
            float xv = x[c];
            xr += w[536 + g * 10 + c] * xv;
            xz += w[536 + (12 + g) * 10 + c] * xv;
            xn += w[536 + (24 + g) * 10 + c] * xv;
        }
        float hr = w[1364 + g], hz = w[1364 + 12 + g], hn = w[1364 + 24 + g];
#pragma unroll
        for (int c = 0; c < 12; ++c) {
            float sv = s[c];
            hr += w[896 + g * 12 + c] * sv;
            hz += w[896 + (12 + g) * 12 + c] * sv;
            hn += w[896 + (24 + g) * 12 + c] * sv;
        }
        float rg = sigf(xr + hr);
        float zg = sigf(xz + hz);
        float ng = tanhf(xn + rg * hn);
        sn[g] = (1.f - zg) * ng + zg * s[g];
    }
#pragma unroll
    for (int c = 0; c < 12; ++c) g_s[(size_t)node * 12 + c] = sn[c];

    float un[8];
#pragma unroll
    for (int o = 0; o < 8; ++o) {
        float v = w[1496 + o];
#pragma unroll
        for (int c = 0; c < 12; ++c) v += w[1400 + o * 12 + c] * sn[c];
        un[o] = v;
    }
    {
        float4* op = (float4*)(uout + (size_t)node * 8);
        op[0] = make_float4(un[0], un[1], un[2], un[3]);
        op[1] = make_float4(un[4], un[5], un[6], un[7]);
    }

    if (last) {
        float hid[16];
#pragma unroll
        for (int t = 0; t < 16; ++t) {
            float h = w[1640 + t];
#pragma unroll
            for (int c = 0; c < 8; ++c) h += w[1512 + t * 8 + c] * un[c];
            hid[t] = fmaxf(h, 0.f);
        }
        float l0 = w[1688], l1 = w[1689];
#pragma unroll
        for (int t = 0; t < 16; ++t) {
            l0 += w[1656 + t] * hid[t];
            l1 += w[1656 + 16 + t] * hid[t];
        }
        float mx = fmaxf(l0, l1);
        float e0 = expf(l0 - mx), e1 = expf(l1 - mx);
        float inv = 1.f / (e0 + e1);
        float p0 = e0 * inv, p1 = e1 * inv;
        const float q0 = -0.70710678118654752440f, q1 = 0.70710678118654752440f;
        float xh = p0 * q0 + p1 * q1;
        float nu = p0 * (q0 - xh) * (q0 - xh) + p1 * (q1 - xh) * (q1 - xh);
        nu = fmaxf(nu, 1e-10f);
        out[node]         = xh;
        out[NNODE + node] = nu;
    }
}

extern "C" void kernel_launch(void* const* d_in, const int* in_sizes, int n_in,
                              void* d_out, int out_size) {
    const float* y    = (const float*)d_in[0];
    const float* H    = (const float*)d_in[1];
    const float* r    = (const float*)d_in[2];
    const float* nur  = (const float*)d_in[3];
    const float* adj  = (const float*)d_in[4];
    const float* W1w  = (const float*)d_in[5];
    const float* W1b  = (const float*)d_in[6];
    const float* b1   = (const float*)d_in[7];
    const float* Wm1  = (const float*)d_in[8];
    const float* Wm1b = (const float*)d_in[9];
    const float* Wm2  = (const float*)d_in[10];
    const float* Wm2b = (const float*)d_in[11];
    const float* wih  = (const float*)d_in[12];
    const float* whh  = (const float*)d_in[13];
    const float* bih  = (const float*)d_in[14];
    const float* bhh  = (const float*)d_in[15];
    const float* W2   = (const float*)d_in[16];
    const float* W2b  = (const float*)d_in[17];
    const float* b2   = (const float*)d_in[18];
    const float* Wr1  = (const float*)d_in[19];
    const float* Wr1b = (const float*)d_in[20];
    const float* Wr2  = (const float*)d_in[21];
    const float* Wr2b = (const float*)d_in[22];
    float* out = (float*)d_out;

    const int GEMM_SMEM = 3 * STAGEB;   // 92160 B
    cudaFuncSetAttribute(k_gemm, cudaFuncAttributeMaxDynamicSharedMemorySize, GEMM_SMEM);

    // fork: k_convcol (H pass) on side stream, k_csr (adj pass) on main stream
    cudaStream_t s2;
    cudaStreamCreateWithFlags(&s2, cudaStreamNonBlocking);
    cudaEvent_t evF, evJ;
    cudaEventCreateWithFlags(&evF, cudaEventDisableTiming);
    cudaEventCreateWithFlags(&evJ, cudaEventDisableTiming);
    cudaEventRecord(evF, 0);
    cudaStreamWaitEvent(s2, evF, 0);
    k_convcol<<<dim3(NB, NN / 128, 8), 128, 0, s2>>>(H, y);
    k_csr<<<NNODE / 8, 256>>>(adj);
    cudaEventRecord(evJ, s2);
    cudaStreamWaitEvent(0, evJ, 0);

    k_gemm<<<dim3(8, 8, NB), 256, GEMM_SMEM>>>(H, W1w, W1b, b1);
    k_node<<<NNODE / 32, 128>>>(r, nur, Wm1, Wm1b, Wm2, Wm2b, wih, whh, bih, bhh,
                                W2, W2b, b2, Wr1, Wr1b, Wr2, Wr2b, 0, 0, out);
    k_node<<<NNODE / 32, 128>>>(r, nur, Wm1, Wm1b, Wm2, Wm2b, wih, whh, bih, bhh,
                                W2, W2b, b2, Wr1, Wr1b, Wr2, Wr2b, 1, 1, out);

    cudaEventDestroy(evF);
    cudaEventDestroy(evJ);
    cudaStreamDestroy(s2);
}

// round 11
// speedup vs baseline: 2.4099x; 1.0308x over previous
#include <cuda_runtime.h>
#include <cuda_fp16.h>
#include <stdint.h>
#include <math.h>

#define FULL 0xffffffffu

static const int NB    = 16;
static const int NN    = 1024;
static const int NNODE = NB * NN;   // 16384
static const int MAXN  = 192;

// -------- static device scratch (no allocations allowed) --------
__device__ float g_u[2][NNODE * 8 + 8];
__device__ float g_s[NNODE * 12];
__device__ float g_yhp[8 * NNODE];
__device__ float g_hhp[8 * NNODE];
__device__ float g_deg[NNODE];
__device__ float g_eg[NNODE];
__device__ int   g_nbru[NNODE * MAXN];
__device__ int   g_cnt[NNODE];
__device__ __half g_Hhi[(size_t)NB * NN * NN];
__device__ __half g_Hlo[(size_t)NB * NN * NN];
__device__ __half g_adjh[(size_t)NB * NN * NN];

__device__ __forceinline__ uint32_t sm_u32(const void* p) {
    uint32_t a;
    asm("{ .reg .u64 t; cvta.to.shared.u64 t, %1; cvt.u32.u64 %0, t; }"
        : "=r"(a) : "l"(p));
    return a;
}
__device__ __forceinline__ void cpasync16(uint32_t dst, const void* src) {
    asm volatile("cp.async.cg.shared.global [%0], [%1], 16;"
                 :: "r"(dst), "l"(src) : "memory");
}
__device__ __forceinline__ void ldsm4(uint32_t& r0, uint32_t& r1, uint32_t& r2,
                                      uint32_t& r3, uint32_t a) {
    asm volatile("ldmatrix.sync.aligned.m8n8.x4.shared.b16 {%0,%1,%2,%3}, [%4];"
                 : "=r"(r0), "=r"(r1), "=r"(r2), "=r"(r3) : "r"(a));
}
__device__ __forceinline__ void mma16816(float* c, uint32_t a0, uint32_t a1,
                                         uint32_t a2, uint32_t a3,
                                         uint32_t b0, uint32_t b1) {
    asm volatile(
        "mma.sync.aligned.m16n8k16.row.col.f32.f16.f16.f32 "
        "{%0,%1,%2,%3}, {%4,%5,%6,%7}, {%8,%9}, {%0,%1,%2,%3};"
        : "+f"(c[0]), "+f"(c[1]), "+f"(c[2]), "+f"(c[3])
        : "r"(a0), "r"(a1), "r"(a2), "r"(a3), "r"(b0), "r"(b1));
}

// fast activations (HW EX2/RCP paths, clamped against overflow)
__device__ __forceinline__ float sigf(float x) {
    float e = __expf(-fmaxf(x, -80.f));
    return __fdividef(1.f, 1.f + e);
}
__device__ __forceinline__ float tanhff(float x) {
    float xc = fminf(fmaxf(x, -15.f), 15.f);
    float t  = __expf(2.f * xc);
    return __fdividef(t - 1.f, t + 1.f);
}

// -------- one pass over H: yh/hh partials + fp16 hi/lo split --------
__global__ void k_convcol(const float* __restrict__ H, const float* __restrict__ y) {
    __shared__ float sy[128];
    int b = blockIdx.x, j = blockIdx.y * 128 + threadIdx.x, k0 = blockIdx.z * 128;
    sy[threadIdx.x] = y[b * NN + k0 + threadIdx.x];
    __syncthreads();
    const float* Hb = H + ((size_t)b * NN + k0) * NN + j;
    __half* hi = g_Hhi + ((size_t)b * NN + k0) * NN + j;
    __half* lo = g_Hlo + ((size_t)b * NN + k0) * NN + j;
    float yh = 0.f, hh = 0.f;
#pragma unroll 4
    for (int i = 0; i < 128; ++i) {
        float h = Hb[(size_t)i * NN];
        __half hb = __float2half(h);
        hi[(size_t)i * NN] = hb;
        lo[(size_t)i * NN] = __float2half(h - __half2float(hb));
        yh += sy[i] * h;
        hh += h * h;
    }
    int node = b * NN + j;
    g_yhp[blockIdx.z * NNODE + node] = yh;
    g_hhp[blockIdx.z * NNODE + node] = hh;
}

// -------- adj pass: neighbor lists + deg + fp16 adj + zero-init --------
__global__ void k_csr(const float* __restrict__ adj) {
    int row  = blockIdx.x * (blockDim.x >> 5) + (threadIdx.x >> 5);
    int lane = threadIdx.x & 31;
    const float* ar = adj + (size_t)row * NN;
    __half* ah = g_adjh + (size_t)row * NN;
    const __half ONE = __float2half(1.f), ZERO = __float2half(0.f);
    int base = row * MAXN;
    int boff = (row >> 10) << 10;
    int cnt  = 0;
    for (int c = 0; c < NN; c += 32) {
        float a = ar[c + lane];
        ah[c + lane] = (a != 0.f) ? ONE : ZERO;
        unsigned m = __ballot_sync(FULL, a != 0.f);
        if (a != 0.f) {
            int pos = cnt + __popc(m & ((1u << lane) - 1u));
            if (pos < MAXN) g_nbru[base + pos] = (boff + c + lane) * 8;
        }
        cnt += __popc(m);
    }
    int cntc = cnt < MAXN ? cnt : MAXN;
    int cntp = (cntc + 3) & ~3;
    if (lane < cntp - cntc) g_nbru[base + cntc + lane] = NNODE * 8;  // zero u row
    if (lane == 0) {
        g_cnt[row] = cntc;
        g_deg[row] = (float)cnt;
        g_eg[row]  = 0.f;
    }
    if (lane < 12) g_s[(size_t)row * 12 + lane] = 0.f;
    if (row == 0 && lane < 8) { g_u[0][NNODE * 8 + lane] = 0.f; g_u[1][NNODE * 8 + lane] = 0.f; }
}

// -------- eg via mma.sync: T = (Hhi+Hlo) @ adj^T, eg_i = sum_k H[k,i]*T[k,i] --
static const int TSTRIDE = 80;              // bytes per tile row (40 halves)
static const int TILEB   = 128 * TSTRIDE;   // 10240 B per tile
static const int STAGEB  = 3 * TILEB;       // Ahi, Alo, B per stage

__global__ void __launch_bounds__(256, 2) k_gemm(const float* __restrict__ H,
                                                 const float* __restrict__ W1w,
                                                 const float* __restrict__ W1b,
                                                 const float* __restrict__ b1) {
    extern __shared__ __align__(16) char smb[];
    const int tid = threadIdx.x, wid = tid >> 5, lane = tid & 31;
    const int g = lane >> 2, t = lane & 3;
    const int b = blockIdx.z;
    const int i0 = blockIdx.x * 128, k0 = blockIdx.y * 128;
    const int wm = wid & 1, wn = wid >> 1;

    // u0 = W1([yh,hh]) finalize on the 128 blocks with blockIdx.y==0
    if (blockIdx.y == 0 && tid < 128) {
        int node = (b * 8 + blockIdx.x) * 128 + tid;
        float yh = 0.f, hh = 0.f;
#pragma unroll
        for (int z = 0; z < 8; ++z) {
            yh += g_yhp[z * NNODE + node];
            hh += g_hhp[z * NNODE + node];
        }
        float* up = &g_u[0][(size_t)node * 8];
#pragma unroll
        for (int c = 0; c < 8; ++c)
            up[c] = W1w[2 * c] * yh + W1w[2 * c + 1] * hh + W1b[c] + b1[c];
    }

    const __half* Ahi = g_Hhi  + ((size_t)b * NN + k0) * NN;
    const __half* Alo = g_Hlo  + ((size_t)b * NN + k0) * NN;
    const __half* Bad = g_adjh + ((size_t)b * NN + i0) * NN;
    const uint32_t sbase = sm_u32(smb);

    const int arow = (lane & 7) + ((lane >> 3) & 1) * 8;
    const int acol = (lane >> 4) * 16;
    const int brow = (lane & 7) + (lane >> 4) * 8;
    const int bcol = ((lane >> 3) & 1) * 16;

    float acc[4][4][4];
#pragma unroll
    for (int a = 0; a < 4; ++a)
#pragma unroll
        for (int n = 0; n < 4; ++n)
#pragma unroll
            for (int r = 0; r < 4; ++r) acc[a][n][r] = 0.f;

    auto issue = [&](int c) {
        int j0 = c * 32;
        uint32_t tb = sbase + (c % 3) * STAGEB;
#pragma unroll
        for (int q = 0; q < 2; ++q) {
            int idx = tid + q * 256;
            int row = idx >> 2, quad = idx & 3;
            uint32_t so = tb + row * TSTRIDE + quad * 16;
            cpasync16(so,             Ahi + (size_t)row * NN + j0 + quad * 8);
            cpasync16(so + TILEB,     Alo + (size_t)row * NN + j0 + quad * 8);
            cpasync16(so + 2 * TILEB, Bad + (size_t)row * NN + j0 + quad * 8);
        }
        asm volatile("cp.async.commit_group;" ::: "memory");
    };

    issue(0);
    issue(1);
    for (int c = 0; c < 32; ++c) {
        if (c < 31) asm volatile("cp.async.wait_group 1;" ::: "memory");
        else        asm volatile("cp.async.wait_group 0;" ::: "memory");
        __syncthreads();
        if (c < 30) issue(c + 2);
        uint32_t sA = sbase + (c % 3) * STAGEB;
        uint32_t sL = sA + TILEB, sB = sA + 2 * TILEB;
#pragma unroll
        for (int ks = 0; ks < 2; ++ks) {
            uint32_t bfr[4][2];
            ldsm4(bfr[0][0], bfr[0][1], bfr[1][0], bfr[1][1],
                  sB + (wn * 32 + brow) * TSTRIDE + ks * 32 + bcol);
            ldsm4(bfr[2][0], bfr[2][1], bfr[3][0], bfr[3][1],
                  sB + (wn * 32 + 16 + brow) * TSTRIDE + ks * 32 + bcol);
#pragma unroll
            for (int sp = 0; sp < 2; ++sp) {
                uint32_t sa = sp ? sL : sA;
#pragma unroll
                for (int mi = 0; mi < 4; ++mi) {
                    uint32_t a0, a1, a2, a3;
                    ldsm4(a0, a1, a2, a3,
                          sa + (wm * 64 + mi * 16 + arow) * TSTRIDE + ks * 32 + acol);
#pragma unroll
                    for (int ni = 0; ni < 4; ++ni)
                        mma16816(acc[mi][ni], a0, a1, a2, a3, bfr[ni][0], bfr[ni][1]);
                }
            }
        }
    }

    const float* Hb = H + ((size_t)b * NN + k0) * NN + i0;
#pragma unroll
    for (int ni = 0; ni < 4; ++ni) {
        int col = wn * 32 + ni * 8 + 2 * t;
        float p0 = 0.f, p1 = 0.f;
#pragma unroll
        for (int mi = 0; mi < 4; ++mi) {
            int m = wm * 64 + mi * 16;
            float2 h0 = *(const float2*)(Hb + (size_t)(m + g) * NN + col);
            float2 h1 = *(const float2*)(Hb + (size_t)(m + g + 8) * NN + col);
            p0 += acc[mi][ni][0] * h0.x + acc[mi][ni][2] * h1.x;
            p1 += acc[mi][ni][1] * h0.y + acc[mi][ni][3] * h1.y;
        }
#pragma unroll
        for (int o = 4; o < 32; o <<= 1) {
            p0 += __shfl_xor_sync(FULL, p0, o);
            p1 += __shfl_xor_sync(FULL, p1, o);
        }
        if (g == 0) {
            atomicAdd(&g_eg[b * NN + i0 + col], p0);
            atomicAdd(&g_eg[b * NN + i0 + col + 1], p1);
        }
    }
}

// -------- fused per-node: 2-phase (128-thread gather, warp-0 compute) ------
// Phase 1: 4 lanes/node gather ns for 32 nodes -> smem. Phase 2: warp 0
// computes 32 nodes with all lanes active (MLP+GRU+W2, readout on last).
__global__ void k_node(const float* __restrict__ r, const float* __restrict__ nur,
                       const float* __restrict__ Wm1, const float* __restrict__ Wm1b,
                       const float* __restrict__ Wm2, const float* __restrict__ Wm2b,
                       const float* __restrict__ wih, const float* __restrict__ whh,
                       const float* __restrict__ bih, const float* __restrict__ bhh,
                       const float* __restrict__ W2,  const float* __restrict__ W2b,
                       const float* __restrict__ b2,
                       const float* __restrict__ Wr1, const float* __restrict__ Wr1b,
                       const float* __restrict__ Wr2, const float* __restrict__ Wr2b,
                       int bufin, int last, float* __restrict__ out) {
    __shared__ float w[1690];
    __shared__ float sns[32][9];
    {
        int t = threadIdx.x;
        for (int i = t; i < 384; i += blockDim.x) w[i]        = Wm1[i];
        for (int i = t; i < 16;  i += blockDim.x) w[384 + i]  = Wm1b[i];
        for (int i = t; i < 128; i += blockDim.x) w[400 + i]  = Wm2[i];
        for (int i = t; i < 8;   i += blockDim.x) w[528 + i]  = Wm2b[i];
        for (int i = t; i < 360; i += blockDim.x) w[536 + i]  = wih[i];
        for (int i = t; i < 432; i += blockDim.x) w[896 + i]  = whh[i];
        for (int i = t; i < 36;  i += blockDim.x) w[1328 + i] = bih[i];
        for (int i = t; i < 36;  i += blockDim.x) w[1364 + i] = bhh[i];
        for (int i = t; i < 96;  i += blockDim.x) w[1400 + i] = W2[i];
        for (int i = t; i < 8;   i += blockDim.x) w[1496 + i] = W2b[i] + b2[i];
        for (int i = t; i < 128; i += blockDim.x) w[1512 + i] = Wr1[i];
        for (int i = t; i < 16;  i += blockDim.x) w[1640 + i] = Wr1b[i];
        for (int i = t; i < 32;  i += blockDim.x) w[1656 + i] = Wr2[i];
        for (int i = t; i < 2;   i += blockDim.x) w[1688 + i] = Wr2b[i];
    }
    __syncthreads();
    const float* uin = g_u[bufin];
    float* uout = g_u[bufin ^ 1];

    // ---- phase 1: gather (4 lanes per node, 32 nodes per block) ----
    {
        int q    = threadIdx.x & 3;
        int nib  = threadIdx.x >> 2;
        int node = blockIdx.x * 32 + nib;
        float ns[8] = {0, 0, 0, 0, 0, 0, 0, 0};
        int nq = ((g_cnt[node] + 3) & ~3) >> 2;
        const int4* off = (const int4*)&g_nbru[node * MAXN];
        for (int i = q; i < nq; i += 4) {
            int4 o = off[i];
            const float4* p0 = (const float4*)(uin + o.x);
            const float4* p1 = (const float4*)(uin + o.y);
            const float4* p2 = (const float4*)(uin + o.z);
            const float4* p3 = (const float4*)(uin + o.w);
            float4 a0 = p0[0], b0 = p0[1];
            float4 a1 = p1[0], b1 = p1[1];
            float4 a2 = p2[0], b2v = p2[1];
            float4 a3 = p3[0], b3 = p3[1];
            ns[0] += a0.x + a1.x + a2.x + a3.x;
            ns[1] += a0.y + a1.y + a2.y + a3.y;
            ns[2] += a0.z + a1.z + a2.z + a3.z;
            ns[3] += a0.w + a1.w + a2.w + a3.w;
            ns[4] += b0.x + b1.x + b2v.x + b3.x;
            ns[5] += b0.y + b1.y + b2v.y + b3.y;
            ns[6] += b0.z + b1.z + b2v.z + b3.z;
            ns[7] += b0.w + b1.w + b2v.w + b3.w;
        }
#pragma unroll
        for (int c = 0; c < 8; ++c) {
            ns[c] += __shfl_xor_sync(FULL, ns[c], 1);
            ns[c] += __shfl_xor_sync(FULL, ns[c], 2);
        }
        if (q == 0) {
#pragma unroll
            for (int c = 0; c < 8; ++c) sns[nib][c] = ns[c];
        }
    }
    __syncthreads();
    if (threadIdx.x >= 32) return;

    // ---- phase 2: warp 0, one node per lane, all lanes active ----
    int lane = threadIdx.x;
    int node = blockIdx.x * 32 + lane;

    float ns[8];
#pragma unroll
    for (int c = 0; c < 8; ++c) ns[c] = sns[lane][c];

    float rv  = r[node];
    float nuv = fmaxf(nur[node], 1e-10f);
    float deg = g_deg[node], eg = g_eg[node];

    float u[8];
    {
        const float4* up = (const float4*)(uin + (size_t)node * 8);
        float4 a = up[0], b4 = up[1];
        u[0] = a.x; u[1] = a.y; u[2] = a.z; u[3] = a.w;
        u[4] = b4.x; u[5] = b4.y; u[6] = b4.z; u[7] = b4.w;
    }

    float m[8];
    {
        float hid[16];
#pragma unroll
        for (int t = 0; t < 16; ++t) {
            float h = w[384 + t];
#pragma unroll
            for (int c = 0; c < 8; ++c) h += w[t * 24 + c] * (u[c] * deg);
#pragma unroll
            for (int c = 0; c < 8; ++c) h += w[t * 24 + 8 + c] * ns[c];
#pragma unroll
            for (int c = 0; c < 8; ++c) h += w[t * 24 + 16 + c] * eg;
            hid[t] = fmaxf(h, 0.f);
        }
#pragma unroll
        for (int o = 0; o < 8; ++o) {
            float v = w[528 + o];
#pragma unroll
            for (int t = 0; t < 16; ++t) v += w[400 + o * 16 + t] * hid[t];
            m[o] = v;
        }
    }

    float x[10];
#pragma unroll
    for (int c = 0; c < 8; ++c) x[c] = m[c];
    x[8] = rv;
    x[9] = nuv;

    float s[12];
#pragma unroll
    for (int c = 0; c < 12; ++c) s[c] = g_s[(size_t)node * 12 + c];

    float sn[12];
#pragma unroll
    for (int g = 0; g < 12; ++g) {
        float xr = w[1328 + g], xz = w[1328 + 12 + g], xn = w[1328 + 24 + g];
#pragma unroll
        for (int c = 0; c < 10; ++c) {
            float xv = x[c];
            xr += w[536 + g * 10 + c] * xv;
            xz += w[536 + (12 + g) * 10 + c] * xv;
            xn += w[536 + (24 + g) * 10 + c] * xv;
        }
        float hr = w[1364 + g], hz = w[1364 + 12 + g], hn = w[1364 + 24 + g];
#pragma unroll
        for (int c = 0; c < 12; ++c) {
            float sv = s[c];
            hr += w[896 + g * 12 + c] * sv;
            hz += w[896 + (12 + g) * 12 + c] * sv;
            hn += w[896 + (24 + g) * 12 + c] * sv;
        }
        float rg = sigf(xr + hr);
        float zg = sigf(xz + hz);
        float ng = tanhff(xn + rg * hn);
        sn[g] = (1.f - zg) * ng + zg * s[g];
    }
#pragma unroll
    for (int c = 0; c < 12; ++c) g_s[(size_t)node * 12 + c] = sn[c];

    float un[8];
#pragma unroll
    for (int o = 0; o < 8; ++o) {
        float v = w[1496 + o];
#pragma unroll
        for (int c = 0; c < 12; ++c) v += w[1400 + o * 12 + c] * sn[c];
        un[o] = v;
    }
    {
        float4* op = (float4*)(uout + (size_t)node * 8);
        op[0] = make_float4(un[0], un[1], un[2], un[3]);
        op[1] = make_float4(un[4], un[5], un[6], un[7]);
    }

    if (last) {
        float hid[16];
#pragma unroll
        for (int t = 0; t < 16; ++t) {
            float h = w[1640 + t];
#pragma unroll
            for (int c = 0; c < 8; ++c) h += w[1512 + t * 8 + c] * un[c];
            hid[t] = fmaxf(h, 0.f);
        }
        float l0 = w[1688], l1 = w[1689];
#pragma unroll
        for (int t = 0; t < 16; ++t) {
            l0 += w[1656 + t] * hid[t];
            l1 += w[1656 + 16 + t] * hid[t];
        }
        float mx = fmaxf(l0, l1);
        float e0 = __expf(l0 - mx), e1 = __expf(l1 - mx);
        float inv = __fdividef(1.f, e0 + e1);
        float p0 = e0 * inv, p1 = e1 * inv;
        const float q0 = -0.70710678118654752440f, q1 = 0.70710678118654752440f;
        float xh = p0 * q0 + p1 * q1;
        float nu = p0 * (q0 - xh) * (q0 - xh) + p1 * (q1 - xh) * (q1 - xh);
        nu = fmaxf(nu, 1e-10f);
        out[node]         = xh;
        out[NNODE + node] = nu;
    }
}

extern "C" void kernel_launch(void* const* d_in, const int* in_sizes, int n_in,
                              void* d_out, int out_size) {
    const float* y    = (const float*)d_in[0];
    const float* H    = (const float*)d_in[1];
    const float* r    = (const float*)d_in[2];
    const float* nur  = (const float*)d_in[3];
    const float* adj  = (const float*)d_in[4];
    const float* W1w  = (const float*)d_in[5];
    const float* W1b  = (const float*)d_in[6];
    const float* b1   = (const float*)d_in[7];
    const float* Wm1  = (const float*)d_in[8];
    const float* Wm1b = (const float*)d_in[9];
    const float* Wm2  = (const float*)d_in[10];
    const float* Wm2b = (const float*)d_in[11];
    const float* wih  = (const float*)d_in[12];
    const float* whh  = (const float*)d_in[13];
    const float* bih  = (const float*)d_in[14];
    const float* bhh  = (const float*)d_in[15];
    const float* W2   = (const float*)d_in[16];
    const float* W2b  = (const float*)d_in[17];
    const float* b2   = (const float*)d_in[18];
    const float* Wr1  = (const float*)d_in[19];
    const float* Wr1b = (const float*)d_in[20];
    const float* Wr2  = (const float*)d_in[21];
    const float* Wr2b = (const float*)d_in[22];
    float* out = (float*)d_out;

    const int GEMM_SMEM = 3 * STAGEB;   // 92160 B
    cudaFuncSetAttribute(k_gemm, cudaFuncAttributeMaxDynamicSharedMemorySize, GEMM_SMEM);

    // fork: k_convcol (H pass) on side stream, k_csr (adj pass) on main stream
    cudaStream_t s2;
    cudaStreamCreateWithFlags(&s2, cudaStreamNonBlocking);
    cudaEvent_t evF, evJ;
    cudaEventCreateWithFlags(&evF, cudaEventDisableTiming);
    cudaEventCreateWithFlags(&evJ, cudaEventDisableTiming);
    cudaEventRecord(evF, 0);
    cudaStreamWaitEvent(s2, evF, 0);
    k_convcol<<<dim3(NB, NN / 128, 8), 128, 0, s2>>>(H, y);
    k_csr<<<NNODE / 8, 256>>>(adj);
    cudaEventRecord(evJ, s2);
    cudaStreamWaitEvent(0, evJ, 0);

    k_gemm<<<dim3(8, 8, NB), 256, GEMM_SMEM>>>(H, W1w, W1b, b1);
    k_node<<<NNODE / 32, 128>>>(r, nur, Wm1, Wm1b, Wm2, Wm2b, wih, whh, bih, bhh,
                                W2, W2b, b2, Wr1, Wr1b, Wr2, Wr2b, 0, 0, out);
    k_node<<<NNODE / 32, 128>>>(r, nur, Wm1, Wm1b, Wm2, Wm2b, wih, whh, bih, bhh,
                                W2, W2b, b2, Wr1, Wr1b, Wr2, Wr2b, 1, 1, out);

    cudaEventDestroy(evF);
    cudaEventDestroy(evJ);
    cudaStreamDestroy(s2);
}